// round 3
// baseline (speedup 1.0000x reference)
#include <cuda_runtime.h>

// ---------------------------------------------------------------------------
// Shapes (fixed for this problem)
// ---------------------------------------------------------------------------
#define B_   4
#define V_   256
#define H_   128      // hidden dim of both EdgeConv layers
#define KE_  32       // edge-attr channels C2
#define JC_  128      // j-chunk processed per phase in ec_kernel
#define ST_T 132      // sT row stride (128 + 4 pad, float4-aligned)
#define ST_E 36       // sE row stride (32 + 4 pad, float4-aligned)
#define H2_  256      // pair-MLP hidden

// ---------------------------------------------------------------------------
// Device scratch (allocation-free rule: __device__ globals)
// ---------------------------------------------------------------------------
__device__ float g_P [B_*V_*H_];
__device__ float g_Q [B_*V_*H_];
__device__ float g_X1[B_*V_*H_];
__device__ float g_X2[B_*V_*H_];
__device__ float g_R [B_*V_*H2_];
__device__ float g_S [B_*V_*H2_];

// ---------------------------------------------------------------------------
// f32x2 packed-FMA helpers (FFMA2: 2 fp32 MACs per instruction on sm_103a)
// ---------------------------------------------------------------------------
using ull = unsigned long long;

__device__ __forceinline__ ull pack2(float x) {
    ull r; asm("mov.b64 %0, {%1, %1};" : "=l"(r) : "f"(x)); return r;
}
__device__ __forceinline__ ull ffma2(ull a, ull b, ull c) {
    ull d; asm("fma.rn.f32x2 %0, %1, %2, %3;" : "=l"(d) : "l"(a), "l"(b), "l"(c));
    return d;
}
__device__ __forceinline__ float2 unpack2(ull v) {
    float2 r; asm("mov.b64 {%0, %1}, %2;" : "=f"(r.x), "=f"(r.y) : "l"(v));
    return r;
}

// ---------------------------------------------------------------------------
// Per-node precompute for an EdgeConv layer:
//   P[n,h] = x[n,:] @ (W1[0:C] - W1[C:2C]) + b1   (x_i coefficient)
//   Q[n,h] = x[n,:] @  W1[C:2C]                    (x_j coefficient)
// ---------------------------------------------------------------------------
__global__ void pq_kernel(const float* __restrict__ x, const float* __restrict__ W1,
                          const float* __restrict__ b1, int C_in,
                          float* __restrict__ P, float* __restrict__ Q)
{
    __shared__ float sx[4][128];
    const int h = threadIdx.x;
    const int base = blockIdx.x * 4;
    #pragma unroll
    for (int r = 0; r < 4; ++r)
        if (h < C_in) sx[r][h] = x[(size_t)(base + r) * C_in + h];
    __syncthreads();

    float bb = b1[h];
    float p0 = bb, p1 = bb, p2 = bb, p3 = bb;
    float q0 = 0.f, q1 = 0.f, q2 = 0.f, q3 = 0.f;
    for (int c = 0; c < C_in; ++c) {
        float wa = W1[c * H_ + h];
        float wb = W1[(C_in + c) * H_ + h];
        float wd = wa - wb;
        p0 += sx[0][c] * wd;  q0 += sx[0][c] * wb;
        p1 += sx[1][c] * wd;  q1 += sx[1][c] * wb;
        p2 += sx[2][c] * wd;  q2 += sx[2][c] * wb;
        p3 += sx[3][c] * wd;  q3 += sx[3][c] * wb;
    }
    P[(size_t)(base+0)*H_ + h] = p0;  Q[(size_t)(base+0)*H_ + h] = q0;
    P[(size_t)(base+1)*H_ + h] = p1;  Q[(size_t)(base+1)*H_ + h] = q1;
    P[(size_t)(base+2)*H_ + h] = p2;  Q[(size_t)(base+2)*H_ + h] = q2;
    P[(size_t)(base+3)*H_ + h] = p3;  Q[(size_t)(base+3)*H_ + h] = q3;
}

// ---------------------------------------------------------------------------
// Fused EdgeConv main kernel. One CTA per (b, i).
//   T[j,c] = relu(P[i,c] + Q[j,c] + e[b,i,j,:] @ W1c)     (phase 1, K=32)
//   H[j,c] = relu(T[j,:] @ W2 + b2)                        (phase 2, K=128)
//   Xout[b,i,c] = masked-max_j H[j,c]   (adj mask; all-masked -> 0)
// 256 threads, 16x16 thread grid, 8x8 register tiles, f32x2 packed FMAs.
// k unrolled x4 with float4 A-operand loads (LDS.128) to cut LDS issue count.
// ---------------------------------------------------------------------------
__global__ void __launch_bounds__(256, 1)
ec_kernel(const float* __restrict__ Pg, const float* __restrict__ Qg,
          const float* __restrict__ E, const float* __restrict__ W1c,
          const float* __restrict__ W2, const float* __restrict__ b2,
          const int* __restrict__ adj, float* __restrict__ Xout)
{
    extern __shared__ float sm[];
    float* sW1c = sm;                        // 32*128      = 4096
    float* sW2  = sW1c + KE_*H_;             // 128*128     = 16384
    float* sT   = sW2  + H_*H_;              // 128*132     = 16896
    float* sE   = sT   + JC_*ST_T;           // 128*36      = 4608
    float* sP   = sE   + JC_*ST_E;           // 128
    float* sB2  = sP   + H_;                 // 128
    int*   sAdj = (int*)(sB2 + H_);          // 256
    float* sRed = sE;                        // reuse (needs 16*128 <= 4608)

    const int tid = threadIdx.x;
    const int bi  = blockIdx.x;              // b*V + i
    const int b   = bi >> 8;

    // stage weights (vectorized)
    {
        const float4* w1 = (const float4*)W1c;
        float4* d1 = (float4*)sW1c;
        #pragma unroll
        for (int idx = tid; idx < KE_*H_/4; idx += 256) d1[idx] = w1[idx];
        const float4* w2 = (const float4*)W2;
        float4* d2 = (float4*)sW2;
        #pragma unroll 4
        for (int idx = tid; idx < H_*H_/4; idx += 256) d2[idx] = w2[idx];
    }
    if (tid < H_) { sP[tid] = Pg[(size_t)bi*H_ + tid]; sB2[tid] = b2[tid]; }
    sAdj[tid] = adj[(size_t)bi*V_ + tid];

    const int ty = tid >> 4, tx = tid & 15;
    const int j0 = ty << 3, c0 = tx << 3;

    float rmax[8];
    #pragma unroll
    for (int p = 0; p < 8; ++p) rmax[p] = -1e9f;

    for (int chunk = 0; chunk < V_/JC_; ++chunk) {
        const int jbase = chunk * JC_;
        __syncthreads();
        // load E chunk (rows jbase..jbase+127) into sE[j][k] (float4)
        {
            const float4* Erow = (const float4*)(E + ((size_t)bi * V_ + jbase) * KE_);
            #pragma unroll
            for (int idx = tid; idx < JC_*KE_/4; idx += 256) {
                int j = idx >> 3, k4 = (idx & 7);
                *(float4*)&sE[j*ST_E + k4*4] = Erow[idx];
            }
        }
        __syncthreads();

        // ---- phase 1: E @ W1c (K=32), k unrolled x4 ----
        ull acc[8][4];
        #pragma unroll
        for (int jj = 0; jj < 8; ++jj)
            #pragma unroll
            for (int p = 0; p < 4; ++p) acc[jj][p] = 0ULL;

        #pragma unroll 2
        for (int k = 0; k < KE_; k += 4) {
            float4 av[8];
            #pragma unroll
            for (int jj = 0; jj < 8; ++jj)
                av[jj] = *(const float4*)&sE[(j0+jj)*ST_E + k];
            #pragma unroll
            for (int kk = 0; kk < 4; ++kk) {
                const ulonglong2 bb0 = *(const ulonglong2*)&sW1c[(k+kk)*H_ + c0];
                const ulonglong2 bb1 = *(const ulonglong2*)&sW1c[(k+kk)*H_ + c0 + 4];
                #pragma unroll
                for (int jj = 0; jj < 8; ++jj) {
                    float as = (kk==0) ? av[jj].x : (kk==1) ? av[jj].y
                             : (kk==2) ? av[jj].z : av[jj].w;
                    ull a2 = pack2(as);
                    acc[jj][0] = ffma2(a2, bb0.x, acc[jj][0]);
                    acc[jj][1] = ffma2(a2, bb0.y, acc[jj][1]);
                    acc[jj][2] = ffma2(a2, bb1.x, acc[jj][2]);
                    acc[jj][3] = ffma2(a2, bb1.y, acc[jj][3]);
                }
            }
        }

        // epilogue: T = relu(acc + P + Q) -> sT (float4 stores)
        {
            float4 pv0 = *(const float4*)&sP[c0];
            float4 pv1 = *(const float4*)&sP[c0 + 4];
            #pragma unroll
            for (int jj = 0; jj < 8; ++jj) {
                const float* q = Qg + ((size_t)b*V_ + jbase + j0 + jj)*H_ + c0;
                float4 q0v = *(const float4*)(q);
                float4 q1v = *(const float4*)(q + 4);
                float2 a0 = unpack2(acc[jj][0]);
                float2 a1 = unpack2(acc[jj][1]);
                float2 a2 = unpack2(acc[jj][2]);
                float2 a3 = unpack2(acc[jj][3]);
                float4 t0, t1;
                t0.x = fmaxf(a0.x + pv0.x + q0v.x, 0.f);
                t0.y = fmaxf(a0.y + pv0.y + q0v.y, 0.f);
                t0.z = fmaxf(a1.x + pv0.z + q0v.z, 0.f);
                t0.w = fmaxf(a1.y + pv0.w + q0v.w, 0.f);
                t1.x = fmaxf(a2.x + pv1.x + q1v.x, 0.f);
                t1.y = fmaxf(a2.y + pv1.y + q1v.y, 0.f);
                t1.z = fmaxf(a3.x + pv1.z + q1v.z, 0.f);
                t1.w = fmaxf(a3.y + pv1.w + q1v.w, 0.f);
                float* trow = sT + (j0+jj)*ST_T + c0;
                *(float4*)(trow)     = t0;
                *(float4*)(trow + 4) = t1;
            }
        }
        __syncthreads();

        // ---- phase 2: T @ W2 (K=128), k unrolled x4 ----
        #pragma unroll
        for (int jj = 0; jj < 8; ++jj)
            #pragma unroll
            for (int p = 0; p < 4; ++p) acc[jj][p] = 0ULL;

        #pragma unroll 2
        for (int k = 0; k < H_; k += 4) {
            float4 av[8];
            #pragma unroll
            for (int jj = 0; jj < 8; ++jj)
                av[jj] = *(const float4*)&sT[(j0+jj)*ST_T + k];
            #pragma unroll
            for (int kk = 0; kk < 4; ++kk) {
                const ulonglong2 bb0 = *(const ulonglong2*)&sW2[(k+kk)*H_ + c0];
                const ulonglong2 bb1 = *(const ulonglong2*)&sW2[(k+kk)*H_ + c0 + 4];
                #pragma unroll
                for (int jj = 0; jj < 8; ++jj) {
                    float as = (kk==0) ? av[jj].x : (kk==1) ? av[jj].y
                             : (kk==2) ? av[jj].z : av[jj].w;
                    ull a2 = pack2(as);
                    acc[jj][0] = ffma2(a2, bb0.x, acc[jj][0]);
                    acc[jj][1] = ffma2(a2, bb0.y, acc[jj][1]);
                    acc[jj][2] = ffma2(a2, bb1.x, acc[jj][2]);
                    acc[jj][3] = ffma2(a2, bb1.y, acc[jj][3]);
                }
            }
        }

        // epilogue: relu(+b2), adjacency-masked running max over j
        #pragma unroll
        for (int jj = 0; jj < 8; ++jj) {
            if (sAdj[jbase + j0 + jj] > 0) {
                #pragma unroll
                for (int p = 0; p < 4; ++p) {
                    float2 hv = unpack2(acc[jj][p]);
                    float h0 = fmaxf(hv.x + sB2[c0+2*p],   0.f);
                    float h1 = fmaxf(hv.y + sB2[c0+2*p+1], 0.f);
                    rmax[2*p]   = fmaxf(rmax[2*p],   h0);
                    rmax[2*p+1] = fmaxf(rmax[2*p+1], h1);
                }
            }
        }
    }

    // cross-thread (over ty / j-tiles) max reduction
    __syncthreads();
    #pragma unroll
    for (int p = 0; p < 8; ++p) sRed[ty*H_ + c0 + p] = rmax[p];
    __syncthreads();
    for (int s = 8; s > 0; s >>= 1) {
        if (ty < s) {
            #pragma unroll
            for (int p = 0; p < 8; ++p) {
                float a = sRed[ty*H_ + c0 + p];
                float o = sRed[(ty+s)*H_ + c0 + p];
                sRed[ty*H_ + c0 + p] = fmaxf(a, o);
            }
        }
        __syncthreads();
    }
    if (ty == 0) {
        #pragma unroll
        for (int p = 0; p < 8; ++p) {
            float v = sRed[c0 + p];
            Xout[(size_t)bi*H_ + c0 + p] = (v < -1e8f) ? 0.f : v;
        }
    }
}

// ---------------------------------------------------------------------------
// Pair-MLP precompute:
//   R[n,m] = x2[n,:] @ h3_W[0:128,  m]            (x_j part)
//   S[n,m] = x2[n,:] @ h3_W[128:256,m] + h3_b[m]  (x_i part)
// ---------------------------------------------------------------------------
__global__ void rs_kernel(const float* __restrict__ x, const float* __restrict__ W3,
                          const float* __restrict__ b3,
                          float* __restrict__ R, float* __restrict__ S)
{
    __shared__ float sx[4][128];
    const int m = threadIdx.x;
    const int base = blockIdx.x * 4;
    if (m < 128) {
        #pragma unroll
        for (int r = 0; r < 4; ++r)
            sx[r][m] = x[(size_t)(base + r) * H_ + m];
    }
    __syncthreads();

    float r0 = 0.f, r1 = 0.f, r2 = 0.f, r3 = 0.f;
    float bb = b3[m];
    float s0 = bb, s1 = bb, s2 = bb, s3 = bb;
    for (int c = 0; c < 128; ++c) {
        float wa = W3[c * H2_ + m];
        float wb = W3[(128 + c) * H2_ + m];
        r0 += sx[0][c]*wa;  s0 += sx[0][c]*wb;
        r1 += sx[1][c]*wa;  s1 += sx[1][c]*wb;
        r2 += sx[2][c]*wa;  s2 += sx[2][c]*wb;
        r3 += sx[3][c]*wa;  s3 += sx[3][c]*wb;
    }
    R[(size_t)(base+0)*H2_ + m] = r0;  S[(size_t)(base+0)*H2_ + m] = s0;
    R[(size_t)(base+1)*H2_ + m] = r1;  S[(size_t)(base+1)*H2_ + m] = s1;
    R[(size_t)(base+2)*H2_ + m] = r2;  S[(size_t)(base+2)*H2_ + m] = s2;
    R[(size_t)(base+3)*H2_ + m] = r3;  S[(size_t)(base+3)*H2_ + m] = s3;
}

// ---------------------------------------------------------------------------
// Pair scoring: out[b,i,j] = sigmoid( sum_m relu(R[j,m]+S[i,m]) * outW[m] + outB )
// ---------------------------------------------------------------------------
#define IL_ 8
#define MC_ 32

__global__ void __launch_bounds__(256)
pair_kernel(const float* __restrict__ R, const float* __restrict__ S,
            const float* __restrict__ outW, const float* __restrict__ outB,
            float* __restrict__ out)
{
    __shared__ float sR[V_][MC_ + 1];
    __shared__ float sS[IL_][MC_ + 1];
    __shared__ float sw[MC_];

    const int tid = threadIdx.x;   // == j
    const int b   = blockIdx.y;
    const int i0  = blockIdx.x * IL_;

    float acc[IL_];
    #pragma unroll
    for (int il = 0; il < IL_; ++il) acc[il] = 0.f;

    for (int mc = 0; mc < H2_; mc += MC_) {
        __syncthreads();
        #pragma unroll 4
        for (int idx = tid; idx < V_*MC_; idx += 256) {
            int j = idx >> 5, mm = idx & (MC_-1);
            sR[j][mm] = R[((size_t)b*V_ + j)*H2_ + mc + mm];
        }
        if (tid < IL_*MC_) {
            int il = tid >> 5, mm = tid & (MC_-1);
            sS[il][mm] = S[((size_t)b*V_ + i0 + il)*H2_ + mc + mm];
        }
        if (tid < MC_) sw[tid] = outW[mc + tid];
        __syncthreads();

        #pragma unroll
        for (int il = 0; il < IL_; ++il) {
            float a = 0.f;
            #pragma unroll
            for (int mm = 0; mm < MC_; ++mm)
                a += fmaxf(sR[tid][mm] + sS[il][mm], 0.f) * sw[mm];
            acc[il] += a;
        }
    }

    const float ob = outB[0];
    #pragma unroll
    for (int il = 0; il < IL_; ++il) {
        float z = acc[il] + ob;
        out[((size_t)b*V_ + i0 + il)*V_ + tid] = 1.f / (1.f + expf(-z));
    }
}

// ---------------------------------------------------------------------------
// Launch
// ---------------------------------------------------------------------------
extern "C" void kernel_launch(void* const* d_in, const int* in_sizes, int n_in,
                              void* d_out, int out_size)
{
    const int*   adj   = (const int*)  d_in[0];
    const float* x0    = (const float*)d_in[1];
    const float* e     = (const float*)d_in[2];
    const float* ec1W1 = (const float*)d_in[3];
    const float* ec1b1 = (const float*)d_in[4];
    const float* ec1W2 = (const float*)d_in[5];
    const float* ec1b2 = (const float*)d_in[6];
    const float* ec2W1 = (const float*)d_in[7];
    const float* ec2b1 = (const float*)d_in[8];
    const float* ec2W2 = (const float*)d_in[9];
    const float* ec2b2 = (const float*)d_in[10];
    const float* h3W   = (const float*)d_in[11];
    const float* h3b   = (const float*)d_in[12];
    const float* outW  = (const float*)d_in[13];
    const float* outB  = (const float*)d_in[14];
    float* out = (float*)d_out;

    float *P, *Q, *X1, *X2, *R, *S;
    cudaGetSymbolAddress((void**)&P,  g_P);
    cudaGetSymbolAddress((void**)&Q,  g_Q);
    cudaGetSymbolAddress((void**)&X1, g_X1);
    cudaGetSymbolAddress((void**)&X2, g_X2);
    cudaGetSymbolAddress((void**)&R,  g_R);
    cudaGetSymbolAddress((void**)&S,  g_S);

    const size_t EC_SMEM =
        (size_t)(KE_*H_ + H_*H_ + JC_*ST_T + JC_*ST_E + H_ + H_ + V_) * sizeof(float);
    cudaFuncSetAttribute(ec_kernel, cudaFuncAttributeMaxDynamicSharedMemorySize,
                         (int)EC_SMEM);

    // EdgeConv #1 (C_in = 64); W1c = rows [2*64, 2*64+32) of ec1_W1
    pq_kernel<<<B_*V_/4, 128>>>(x0, ec1W1, ec1b1, 64, P, Q);
    ec_kernel<<<B_*V_, 256, EC_SMEM>>>(P, Q, e, ec1W1 + 2*64*H_, ec1W2, ec1b2, adj, X1);

    // EdgeConv #2 (C_in = 128); W1c = rows [2*128, 2*128+32) of ec2_W1
    pq_kernel<<<B_*V_/4, 128>>>(X1, ec2W1, ec2b1, 128, P, Q);
    ec_kernel<<<B_*V_, 256, EC_SMEM>>>(P, Q, e, ec2W1 + 2*128*H_, ec2W2, ec2b2, adj, X2);

    // Pair scoring
    rs_kernel<<<B_*V_/4, 256>>>(X2, h3W, h3b, R, S);
    dim3 pg(V_/IL_, B_);
    pair_kernel<<<pg, 256>>>(R, S, outW, outB, out);
}

// round 5
// speedup vs baseline: 1.5566x; 1.5566x over previous
#include <cuda_runtime.h>
#include <cuda_bf16.h>
#include <cstdint>

#define B_   4
#define V_   256
#define H_   128
#define KE_  32
#define H2_  256
#define ST_W 136    // bf16 row stride for W1/W2/T tiles (conflict-free for ldmatrix)
#define ST_E2 40    // bf16 row stride for E tiles

__device__ float g_P [B_*V_*H_];
__device__ float g_Q [B_*V_*H_];
__device__ float g_X1[B_*V_*H_];
__device__ float g_X2[B_*V_*H_];
__device__ float g_R [B_*V_*H2_];
__device__ float g_S [B_*V_*H2_];
// padded hi/lo bf16 weight tiles, [k][c] row-major with stride ST_W
__device__ __align__(16) unsigned short g_w1hi[2][KE_*ST_W];
__device__ __align__(16) unsigned short g_w1lo[2][KE_*ST_W];
__device__ __align__(16) unsigned short g_w2hi[2][H_*ST_W];
__device__ __align__(16) unsigned short g_w2lo[2][H_*ST_W];

__device__ __forceinline__ unsigned short bf16b(float f) {
    __nv_bfloat16 h = __float2bfloat16(f);
    return *(unsigned short*)&h;
}
__device__ __forceinline__ float bf16f(unsigned short u) {
    __nv_bfloat16 h = *(__nv_bfloat16*)&u;
    return __bfloat162float(h);
}
__device__ __forceinline__ uint32_t smem_to_u32(const void* p) {
    uint32_t a;
    asm("{ .reg .u64 t; cvta.to.shared.u64 t, %1; cvt.u32.u64 %0, t; }" : "=r"(a) : "l"(p));
    return a;
}
__device__ __forceinline__ void ldsm4(uint32_t* r, uint32_t a) {
    asm volatile("ldmatrix.sync.aligned.m8n8.x4.shared.b16 {%0,%1,%2,%3}, [%4];"
        : "=r"(r[0]), "=r"(r[1]), "=r"(r[2]), "=r"(r[3]) : "r"(a));
}
__device__ __forceinline__ void ldsm4t(uint32_t* r, uint32_t a) {
    asm volatile("ldmatrix.sync.aligned.m8n8.x4.trans.shared.b16 {%0,%1,%2,%3}, [%4];"
        : "=r"(r[0]), "=r"(r[1]), "=r"(r[2]), "=r"(r[3]) : "r"(a));
}
__device__ __forceinline__ void mma_bf16(float* c, const uint32_t* a, const uint32_t* b) {
    asm volatile("mma.sync.aligned.m16n8k16.row.col.f32.bf16.bf16.f32 "
        "{%0,%1,%2,%3}, {%4,%5,%6,%7}, {%8,%9}, {%0,%1,%2,%3};"
        : "+f"(c[0]), "+f"(c[1]), "+f"(c[2]), "+f"(c[3])
        : "r"(a[0]), "r"(a[1]), "r"(a[2]), "r"(a[3]), "r"(b[0]), "r"(b[1]));
}

// SMEM byte offsets
#define OFF_P     0
#define OFF_B2    512
#define OFF_ADJ   1024
#define OFF_RED   2048
#define OFF_W1HI  6144
#define OFF_W1LO  14848
#define OFF_W2HI  23552
#define OFF_W2LO  58368
#define OFF_EHI   93184
#define OFF_ELO   103424
#define OFF_THI   113664
#define OFF_TLO   148480
#define SMEM_EC   183296

// ---------------------------------------------------------------------------
// Weight prep: W1c = rows [2C, 2C+32) of ec W1 (the e_ij part), W2 full.
// Decompose to bf16 hi/lo, store padded [k][c] row-major, stride ST_W.
// ---------------------------------------------------------------------------
__global__ void prep_w(const float* __restrict__ W1, int C, const float* __restrict__ W2,
                       unsigned short* __restrict__ w1h, unsigned short* __restrict__ w1l,
                       unsigned short* __restrict__ w2h, unsigned short* __restrict__ w2l)
{
    int idx = blockIdx.x * blockDim.x + threadIdx.x;
    if (idx < KE_*H_) {
        int k = idx >> 7, c = idx & 127;
        float w = W1[(size_t)(2*C + k)*H_ + c];
        unsigned short h = bf16b(w);
        w1h[k*ST_W + c] = h;  w1l[k*ST_W + c] = bf16b(w - bf16f(h));
    } else if (idx < KE_*H_ + H_*H_) {
        int t = idx - KE_*H_;
        int k = t >> 7, c = t & 127;
        float w = W2[(size_t)k*H_ + c];
        unsigned short h = bf16b(w);
        w2h[k*ST_W + c] = h;  w2l[k*ST_W + c] = bf16b(w - bf16f(h));
    }
}

// ---------------------------------------------------------------------------
__global__ void pq_kernel(const float* __restrict__ x, const float* __restrict__ W1,
                          const float* __restrict__ b1, int C_in,
                          float* __restrict__ P, float* __restrict__ Q)
{
    __shared__ float sx[4][128];
    const int h = threadIdx.x;
    const int base = blockIdx.x * 4;
    #pragma unroll
    for (int r = 0; r < 4; ++r)
        if (h < C_in) sx[r][h] = x[(size_t)(base + r) * C_in + h];
    __syncthreads();
    float bb = b1[h];
    float p0=bb,p1=bb,p2=bb,p3=bb, q0=0.f,q1=0.f,q2=0.f,q3=0.f;
    for (int c = 0; c < C_in; ++c) {
        float wa = W1[c*H_ + h], wb = W1[(C_in+c)*H_ + h], wd = wa - wb;
        p0 += sx[0][c]*wd; q0 += sx[0][c]*wb;
        p1 += sx[1][c]*wd; q1 += sx[1][c]*wb;
        p2 += sx[2][c]*wd; q2 += sx[2][c]*wb;
        p3 += sx[3][c]*wd; q3 += sx[3][c]*wb;
    }
    P[(size_t)(base+0)*H_+h]=p0; Q[(size_t)(base+0)*H_+h]=q0;
    P[(size_t)(base+1)*H_+h]=p1; Q[(size_t)(base+1)*H_+h]=q1;
    P[(size_t)(base+2)*H_+h]=p2; Q[(size_t)(base+2)*H_+h]=q2;
    P[(size_t)(base+3)*H_+h]=p3; Q[(size_t)(base+3)*H_+h]=q3;
}

// ---------------------------------------------------------------------------
// Fused EdgeConv on HMMA (mma.sync m16n8k16 bf16, split-bf16 3-term).
// One CTA per (b,i), 256 threads = 8 warps; warp w owns rows j = 16w..16w+15.
// ---------------------------------------------------------------------------
__global__ void __launch_bounds__(256, 1)
ec_hmma(const float* __restrict__ Pg, const float* __restrict__ Qg,
        const float* __restrict__ E, const float* __restrict__ b2,
        const int* __restrict__ adj, float* __restrict__ Xout, int layer)
{
    extern __shared__ char smem[];
    const uint32_t sb = smem_to_u32(smem);
    const int tid = threadIdx.x, w = tid >> 5, lane = tid & 31;
    const int g = lane >> 2, tg = lane & 3;
    const int bi = blockIdx.x, b = bi >> 8;
    const int j0 = w * 16;
    const int rowsel = lane & 15, colsel = (lane >> 4) * 8;

    {   // stage weight tiles
        const uint4* s; uint4* d;
        s = (const uint4*)g_w1hi[layer]; d = (uint4*)(smem + OFF_W1HI);
        for (int i = tid; i < 544;  i += 256) d[i] = s[i];
        s = (const uint4*)g_w1lo[layer]; d = (uint4*)(smem + OFF_W1LO);
        for (int i = tid; i < 544;  i += 256) d[i] = s[i];
        s = (const uint4*)g_w2hi[layer]; d = (uint4*)(smem + OFF_W2HI);
        for (int i = tid; i < 2176; i += 256) d[i] = s[i];
        s = (const uint4*)g_w2lo[layer]; d = (uint4*)(smem + OFF_W2LO);
        for (int i = tid; i < 2176; i += 256) d[i] = s[i];
    }
    float* sPf  = (float*)(smem + OFF_P);
    float* sB2f = (float*)(smem + OFF_B2);
    int*   sAdj = (int*)(smem + OFF_ADJ);
    if (tid < H_) { sPf[tid] = Pg[(size_t)bi*H_ + tid]; sB2f[tid] = b2[tid]; }
    sAdj[tid] = adj[(size_t)bi*V_ + tid];

    float rmax[32];
    #pragma unroll
    for (int i = 0; i < 32; ++i) rmax[i] = -1e9f;

    for (int chunk = 0; chunk < 2; ++chunk) {
        const int jbase = chunk * 128;
        __syncthreads();
        // ---- stage E chunk -> hi/lo bf16 tiles (stride ST_E2) ----
        for (int idx = tid; idx < 1024; idx += 256) {
            int j = idx >> 3, kq = idx & 7;
            float4 e4 = *(const float4*)(E + (((size_t)bi*V_) + jbase + j)*KE_ + kq*4);
            unsigned short h0=bf16b(e4.x), h1=bf16b(e4.y), h2=bf16b(e4.z), h3=bf16b(e4.w);
            uint2 hp, lp;
            hp.x = (uint32_t)h0 | ((uint32_t)h1 << 16);
            hp.y = (uint32_t)h2 | ((uint32_t)h3 << 16);
            lp.x = (uint32_t)bf16b(e4.x-bf16f(h0)) | ((uint32_t)bf16b(e4.y-bf16f(h1)) << 16);
            lp.y = (uint32_t)bf16b(e4.z-bf16f(h2)) | ((uint32_t)bf16b(e4.w-bf16f(h3)) << 16);
            uint32_t o = (uint32_t)(j*ST_E2 + kq*4) * 2u;
            *(uint2*)(smem + OFF_EHI + o) = hp;
            *(uint2*)(smem + OFF_ELO + o) = lp;
        }
        __syncthreads();

        float acc[16][4];
        #pragma unroll
        for (int n = 0; n < 16; ++n)
            #pragma unroll
            for (int p = 0; p < 4; ++p) acc[n][p] = 0.f;

        // ---- phase 1: E @ W1c (K=32) ----
        #pragma unroll
        for (int ks = 0; ks < 2; ++ks) {
            const int k0 = ks * 16;
            uint32_t aH[4], aL[4];
            uint32_t ao = (uint32_t)((j0 + rowsel)*ST_E2 + k0 + colsel) * 2u;
            ldsm4(aH, sb + OFF_EHI + ao);
            ldsm4(aL, sb + OFF_ELO + ao);
            const uint32_t brow = (uint32_t)((k0 + rowsel)*ST_W + colsel) * 2u;
            #pragma unroll
            for (int ntp = 0; ntp < 8; ++ntp) {
                uint32_t bo = brow + (uint32_t)(ntp*16*2);
                uint32_t bH[4], bL[4];
                ldsm4t(bH, sb + OFF_W1HI + bo);
                ldsm4t(bL, sb + OFF_W1LO + bo);
                mma_bf16(acc[2*ntp],   aH, &bH[0]);
                mma_bf16(acc[2*ntp],   aH, &bL[0]);
                mma_bf16(acc[2*ntp],   aL, &bH[0]);
                mma_bf16(acc[2*ntp+1], aH, &bH[2]);
                mma_bf16(acc[2*ntp+1], aH, &bL[2]);
                mma_bf16(acc[2*ntp+1], aL, &bH[2]);
            }
        }

        // ---- epilogue 1: T = relu(P + Q + D) -> hi/lo tiles ----
        {
            const int jA = j0 + g, jB = j0 + 8 + g;
            const float* qA = Qg + ((size_t)(b*V_ + jbase + jA))*H_;
            const float* qB = Qg + ((size_t)(b*V_ + jbase + jB))*H_;
            #pragma unroll
            for (int nt = 0; nt < 16; ++nt) {
                const int c = nt*8 + tg*2;
                float2 q0 = *(const float2*)(qA + c);
                float2 q1 = *(const float2*)(qB + c);
                float pc0 = sPf[c], pc1 = sPf[c+1];
                float t0 = fmaxf(acc[nt][0] + pc0 + q0.x, 0.f);
                float t1 = fmaxf(acc[nt][1] + pc1 + q0.y, 0.f);
                float t2 = fmaxf(acc[nt][2] + pc0 + q1.x, 0.f);
                float t3 = fmaxf(acc[nt][3] + pc1 + q1.y, 0.f);
                unsigned short h0=bf16b(t0), h1=bf16b(t1), h2=bf16b(t2), h3=bf16b(t3);
                uint32_t oA = (uint32_t)(jA*ST_W + c) * 2u;
                uint32_t oB = (uint32_t)(jB*ST_W + c) * 2u;
                *(uint32_t*)(smem + OFF_THI + oA) = (uint32_t)h0 | ((uint32_t)h1 << 16);
                *(uint32_t*)(smem + OFF_TLO + oA) =
                    (uint32_t)bf16b(t0-bf16f(h0)) | ((uint32_t)bf16b(t1-bf16f(h1)) << 16);
                *(uint32_t*)(smem + OFF_THI + oB) = (uint32_t)h2 | ((uint32_t)h3 << 16);
                *(uint32_t*)(smem + OFF_TLO + oB) =
                    (uint32_t)bf16b(t2-bf16f(h2)) | ((uint32_t)bf16b(t3-bf16f(h3)) << 16);
            }
        }
        __syncwarp();   // T rows are per-warp private: warp-level ordering suffices

        #pragma unroll
        for (int n = 0; n < 16; ++n)
            #pragma unroll
            for (int p = 0; p < 4; ++p) acc[n][p] = 0.f;

        // ---- phase 2: T @ W2 (K=128) ----
        #pragma unroll
        for (int ks = 0; ks < 8; ++ks) {
            const int k0 = ks * 16;
            uint32_t aH[4], aL[4];
            uint32_t ao = (uint32_t)((j0 + rowsel)*ST_W + k0 + colsel) * 2u;
            ldsm4(aH, sb + OFF_THI + ao);
            ldsm4(aL, sb + OFF_TLO + ao);
            const uint32_t brow = (uint32_t)((k0 + rowsel)*ST_W + colsel) * 2u;
            #pragma unroll
            for (int ntp = 0; ntp < 8; ++ntp) {
                uint32_t bo = brow + (uint32_t)(ntp*16*2);
                uint32_t bH[4], bL[4];
                ldsm4t(bH, sb + OFF_W2HI + bo);
                ldsm4t(bL, sb + OFF_W2LO + bo);
                mma_bf16(acc[2*ntp],   aH, &bH[0]);
                mma_bf16(acc[2*ntp],   aH, &bL[0]);
                mma_bf16(acc[2*ntp],   aL, &bH[0]);
                mma_bf16(acc[2*ntp+1], aH, &bH[2]);
                mma_bf16(acc[2*ntp+1], aH, &bL[2]);
                mma_bf16(acc[2*ntp+1], aL, &bH[2]);
            }
        }

        // ---- epilogue 2: relu(+b2), adjacency-masked col-max ----
        {
            const bool actA = sAdj[jbase + j0 + g] > 0;
            const bool actB = sAdj[jbase + j0 + 8 + g] > 0;
            #pragma unroll
            for (int nt = 0; nt < 16; ++nt) {
                const int c = nt*8 + tg*2;
                float b0 = sB2f[c], b1 = sB2f[c+1];
                if (actA) {
                    rmax[2*nt]   = fmaxf(rmax[2*nt],   fmaxf(acc[nt][0]+b0, 0.f));
                    rmax[2*nt+1] = fmaxf(rmax[2*nt+1], fmaxf(acc[nt][1]+b1, 0.f));
                }
                if (actB) {
                    rmax[2*nt]   = fmaxf(rmax[2*nt],   fmaxf(acc[nt][2]+b0, 0.f));
                    rmax[2*nt+1] = fmaxf(rmax[2*nt+1], fmaxf(acc[nt][3]+b1, 0.f));
                }
            }
        }
    }

    // reduce over g (lanes differing in bits 2..4), then over warps via smem
    #pragma unroll
    for (int off = 4; off <= 16; off <<= 1)
        #pragma unroll
        for (int i = 0; i < 32; ++i)
            rmax[i] = fmaxf(rmax[i], __shfl_xor_sync(0xffffffffu, rmax[i], off));

    float* red = (float*)(smem + OFF_RED);
    if (lane < 4) {
        #pragma unroll
        for (int nt = 0; nt < 16; ++nt) {
            red[w*H_ + nt*8 + lane*2]     = rmax[2*nt];
            red[w*H_ + nt*8 + lane*2 + 1] = rmax[2*nt+1];
        }
    }
    __syncthreads();
    if (tid < H_) {
        float v = red[tid];
        #pragma unroll
        for (int ww = 1; ww < 8; ++ww) v = fmaxf(v, red[ww*H_ + tid]);
        Xout[(size_t)bi*H_ + tid] = (v < -1e8f) ? 0.f : v;
    }
}

// ---------------------------------------------------------------------------
__global__ void rs_kernel(const float* __restrict__ x, const float* __restrict__ W3,
                          const float* __restrict__ b3,
                          float* __restrict__ R, float* __restrict__ S)
{
    __shared__ float sx[4][128];
    const int m = threadIdx.x;
    const int base = blockIdx.x * 4;
    if (m < 128) {
        #pragma unroll
        for (int r = 0; r < 4; ++r) sx[r][m] = x[(size_t)(base + r)*H_ + m];
    }
    __syncthreads();
    float r0=0.f,r1=0.f,r2=0.f,r3=0.f;
    float bb = b3[m];
    float s0=bb,s1=bb,s2=bb,s3=bb;
    for (int c = 0; c < 128; ++c) {
        float wa = W3[c*H2_ + m], wb = W3[(128+c)*H2_ + m];
        r0 += sx[0][c]*wa; s0 += sx[0][c]*wb;
        r1 += sx[1][c]*wa; s1 += sx[1][c]*wb;
        r2 += sx[2][c]*wa; s2 += sx[2][c]*wb;
        r3 += sx[3][c]*wa; s3 += sx[3][c]*wb;
    }
    R[(size_t)(base+0)*H2_+m]=r0; S[(size_t)(base+0)*H2_+m]=s0;
    R[(size_t)(base+1)*H2_+m]=r1; S[(size_t)(base+1)*H2_+m]=s1;
    R[(size_t)(base+2)*H2_+m]=r2; S[(size_t)(base+2)*H2_+m]=s2;
    R[(size_t)(base+3)*H2_+m]=r3; S[(size_t)(base+3)*H2_+m]=s3;
}

#define IL_ 8
#define MC_ 32
__global__ void __launch_bounds__(256)
pair_kernel(const float* __restrict__ R, const float* __restrict__ S,
            const float* __restrict__ outW, const float* __restrict__ outB,
            float* __restrict__ out)
{
    __shared__ float sR[V_][MC_+1];
    __shared__ float sS[IL_][MC_+1];
    __shared__ float sw[MC_];
    const int tid = threadIdx.x;
    const int b = blockIdx.y, i0 = blockIdx.x * IL_;
    float acc[IL_];
    #pragma unroll
    for (int il = 0; il < IL_; ++il) acc[il] = 0.f;

    for (int mc = 0; mc < H2_; mc += MC_) {
        __syncthreads();
        #pragma unroll 4
        for (int idx = tid; idx < V_*MC_; idx += 256) {
            int j = idx >> 5, mm = idx & (MC_-1);
            sR[j][mm] = R[((size_t)b*V_ + j)*H2_ + mc + mm];
        }
        if (tid < IL_*MC_) {
            int il = tid >> 5, mm = tid & (MC_-1);
            sS[il][mm] = S[((size_t)b*V_ + i0 + il)*H2_ + mc + mm];
        }
        if (tid < MC_) sw[tid] = outW[mc + tid];
        __syncthreads();
        #pragma unroll
        for (int il = 0; il < IL_; ++il) {
            float a = 0.f;
            #pragma unroll
            for (int mm = 0; mm < MC_; ++mm)
                a += fmaxf(sR[tid][mm] + sS[il][mm], 0.f) * sw[mm];
            acc[il] += a;
        }
    }
    const float ob = outB[0];
    #pragma unroll
    for (int il = 0; il < IL_; ++il) {
        float z = acc[il] + ob;
        out[((size_t)b*V_ + i0 + il)*V_ + tid] = 1.f / (1.f + expf(-z));
    }
}

// ---------------------------------------------------------------------------
extern "C" void kernel_launch(void* const* d_in, const int* in_sizes, int n_in,
                              void* d_out, int out_size)
{
    const int*   adj   = (const int*)  d_in[0];
    const float* x0    = (const float*)d_in[1];
    const float* e     = (const float*)d_in[2];
    const float* ec1W1 = (const float*)d_in[3];
    const float* ec1b1 = (const float*)d_in[4];
    const float* ec1W2 = (const float*)d_in[5];
    const float* ec1b2 = (const float*)d_in[6];
    const float* ec2W1 = (const float*)d_in[7];
    const float* ec2b1 = (const float*)d_in[8];
    const float* ec2W2 = (const float*)d_in[9];
    const float* ec2b2 = (const float*)d_in[10];
    const float* h3W   = (const float*)d_in[11];
    const float* h3b   = (const float*)d_in[12];
    const float* outW  = (const float*)d_in[13];
    const float* outB  = (const float*)d_in[14];
    float* out = (float*)d_out;

    float *P, *Q, *X1, *X2, *R, *S;
    cudaGetSymbolAddress((void**)&P,  g_P);
    cudaGetSymbolAddress((void**)&Q,  g_Q);
    cudaGetSymbolAddress((void**)&X1, g_X1);
    cudaGetSymbolAddress((void**)&X2, g_X2);
    cudaGetSymbolAddress((void**)&R,  g_R);
    cudaGetSymbolAddress((void**)&S,  g_S);
    unsigned short *w1h0,*w1l0,*w2h0,*w2l0;
    cudaGetSymbolAddress((void**)&w1h0, g_w1hi);
    cudaGetSymbolAddress((void**)&w1l0, g_w1lo);
    cudaGetSymbolAddress((void**)&w2h0, g_w2hi);
    cudaGetSymbolAddress((void**)&w2l0, g_w2lo);

    cudaFuncSetAttribute(ec_hmma, cudaFuncAttributeMaxDynamicSharedMemorySize, SMEM_EC);

    const int PREP_N = (KE_*H_ + H_*H_ + 255) / 256;
    prep_w<<<PREP_N, 256>>>(ec1W1, 64,  ec1W2, w1h0, w1l0, w2h0, w2l0);
    prep_w<<<PREP_N, 256>>>(ec2W1, 128, ec2W2,
                            w1h0 + KE_*ST_W, w1l0 + KE_*ST_W,
                            w2h0 + H_*ST_W,  w2l0 + H_*ST_W);

    pq_kernel<<<B_*V_/4, 128>>>(x0, ec1W1, ec1b1, 64, P, Q);
    ec_hmma<<<B_*V_, 256, SMEM_EC>>>(P, Q, e, ec1b2, adj, X1, 0);

    pq_kernel<<<B_*V_/4, 128>>>(X1, ec2W1, ec2b1, 128, P, Q);
    ec_hmma<<<B_*V_, 256, SMEM_EC>>>(P, Q, e, ec2b2, adj, X2, 1);

    rs_kernel<<<B_*V_/4, 256>>>(X2, h3W, h3b, R, S);
    dim3 pg(V_/IL_, B_);
    pair_kernel<<<pg, 256>>>(R, S, outW, outB, out);
}

// round 6
// speedup vs baseline: 1.6932x; 1.0877x over previous
#include <cuda_runtime.h>
#include <cuda_bf16.h>
#include <cstdint>

#define B_   4
#define V_   256
#define H_   128
#define KE_  32
#define H2_  256
#define ST_W 136    // bf16 row stride for W1/W2 tiles (272B = 17*16, ldmatrix conflict-free)
#define ST_E2 40    // bf16 row stride for E tiles (80B = 5*16)

__device__ float g_P [B_*V_*H_];
__device__ float g_Q [B_*V_*H_];
__device__ float g_X1[B_*V_*H_];
__device__ float g_X2[B_*V_*H_];
__device__ float g_R [B_*V_*H2_];
__device__ float g_S [B_*V_*H2_];
__device__ __align__(16) unsigned short g_w1hi[2][KE_*ST_W];
__device__ __align__(16) unsigned short g_w1lo[2][KE_*ST_W];
__device__ __align__(16) unsigned short g_w2hi[2][H_*ST_W];
__device__ __align__(16) unsigned short g_w2lo[2][H_*ST_W];

__device__ __forceinline__ unsigned short bf16b(float f) {
    __nv_bfloat16 h = __float2bfloat16(f);
    return *(unsigned short*)&h;
}
__device__ __forceinline__ float bf16f(unsigned short u) {
    __nv_bfloat16 h = *(__nv_bfloat16*)&u;
    return __bfloat162float(h);
}
__device__ __forceinline__ uint32_t smem_to_u32(const void* p) {
    uint32_t a;
    asm("{ .reg .u64 t; cvta.to.shared.u64 t, %1; cvt.u32.u64 %0, t; }" : "=r"(a) : "l"(p));
    return a;
}
__device__ __forceinline__ void ldsm4(uint32_t* r, uint32_t a) {
    asm volatile("ldmatrix.sync.aligned.m8n8.x4.shared.b16 {%0,%1,%2,%3}, [%4];"
        : "=r"(r[0]), "=r"(r[1]), "=r"(r[2]), "=r"(r[3]) : "r"(a));
}
__device__ __forceinline__ void ldsm4t(uint32_t* r, uint32_t a) {
    asm volatile("ldmatrix.sync.aligned.m8n8.x4.trans.shared.b16 {%0,%1,%2,%3}, [%4];"
        : "=r"(r[0]), "=r"(r[1]), "=r"(r[2]), "=r"(r[3]) : "r"(a));
}
__device__ __forceinline__ void mma_bf16(float* c, const uint32_t* a, const uint32_t* b) {
    asm volatile("mma.sync.aligned.m16n8k16.row.col.f32.bf16.bf16.f32 "
        "{%0,%1,%2,%3}, {%4,%5,%6,%7}, {%8,%9}, {%0,%1,%2,%3};"
        : "+f"(c[0]), "+f"(c[1]), "+f"(c[2]), "+f"(c[3])
        : "r"(a[0]), "r"(a[1]), "r"(a[2]), "r"(a[3]), "r"(b[0]), "r"(b[1]));
}

// SMEM byte offsets (no T tile any more — phase2 A comes from registers)
#define OFF_P     0
#define OFF_B2    512
#define OFF_ADJ   1024
#define OFF_RED   2048
#define OFF_W1HI  6144
#define OFF_W1LO  14848
#define OFF_W2HI  23552
#define OFF_W2LO  58368
#define OFF_EHI   93184
#define OFF_ELO   103424
#define SMEM_EC   113664

// ---------------------------------------------------------------------------
__global__ void prep_w(const float* __restrict__ W1, int C, const float* __restrict__ W2,
                       unsigned short* __restrict__ w1h, unsigned short* __restrict__ w1l,
                       unsigned short* __restrict__ w2h, unsigned short* __restrict__ w2l)
{
    int idx = blockIdx.x * blockDim.x + threadIdx.x;
    if (idx < KE_*H_) {
        int k = idx >> 7, c = idx & 127;
        float w = W1[(size_t)(2*C + k)*H_ + c];
        unsigned short h = bf16b(w);
        w1h[k*ST_W + c] = h;  w1l[k*ST_W + c] = bf16b(w - bf16f(h));
    } else if (idx < KE_*H_ + H_*H_) {
        int t = idx - KE_*H_;
        int k = t >> 7, c = t & 127;
        float w = W2[(size_t)k*H_ + c];
        unsigned short h = bf16b(w);
        w2h[k*ST_W + c] = h;  w2l[k*ST_W + c] = bf16b(w - bf16f(h));
    }
}

// ---------------------------------------------------------------------------
__global__ void pq_kernel(const float* __restrict__ x, const float* __restrict__ W1,
                          const float* __restrict__ b1, int C_in,
                          float* __restrict__ P, float* __restrict__ Q)
{
    __shared__ float sx[4][128];
    const int h = threadIdx.x;
    const int base = blockIdx.x * 4;
    #pragma unroll
    for (int r = 0; r < 4; ++r)
        if (h < C_in) sx[r][h] = x[(size_t)(base + r) * C_in + h];
    __syncthreads();
    float bb = b1[h];
    float p0=bb,p1=bb,p2=bb,p3=bb, q0=0.f,q1=0.f,q2=0.f,q3=0.f;
    for (int c = 0; c < C_in; ++c) {
        float wa = W1[c*H_ + h], wb = W1[(C_in+c)*H_ + h], wd = wa - wb;
        p0 += sx[0][c]*wd; q0 += sx[0][c]*wb;
        p1 += sx[1][c]*wd; q1 += sx[1][c]*wb;
        p2 += sx[2][c]*wd; q2 += sx[2][c]*wb;
        p3 += sx[3][c]*wd; q3 += sx[3][c]*wb;
    }
    P[(size_t)(base+0)*H_+h]=p0; Q[(size_t)(base+0)*H_+h]=q0;
    P[(size_t)(base+1)*H_+h]=p1; Q[(size_t)(base+1)*H_+h]=q1;
    P[(size_t)(base+2)*H_+h]=p2; Q[(size_t)(base+2)*H_+h]=q2;
    P[(size_t)(base+3)*H_+h]=p3; Q[(size_t)(base+3)*H_+h]=q3;
}

// ---------------------------------------------------------------------------
// Fused EdgeConv on HMMA, T kept entirely in registers between phases.
// One CTA per (b,i), 256 threads = 8 warps; warp w owns rows j = 16w..16w+15.
// ---------------------------------------------------------------------------
__global__ void __launch_bounds__(256, 1)
ec_hmma(const float* __restrict__ Pg, const float* __restrict__ Qg,
        const float* __restrict__ E, const float* __restrict__ b2,
        const int* __restrict__ adj, float* __restrict__ Xout, int layer)
{
    extern __shared__ char smem[];
    const uint32_t sb = smem_to_u32(smem);
    const int tid = threadIdx.x, w = tid >> 5, lane = tid & 31;
    const int g = lane >> 2, tg = lane & 3;
    const int bi = blockIdx.x, b = bi >> 8;
    const int j0 = w * 16;
    const int rowsel = lane & 15, colsel = (lane >> 4) * 8;

    {   // stage weight tiles
        const uint4* s; uint4* d;
        s = (const uint4*)g_w1hi[layer]; d = (uint4*)(smem + OFF_W1HI);
        for (int i = tid; i < 544;  i += 256) d[i] = s[i];
        s = (const uint4*)g_w1lo[layer]; d = (uint4*)(smem + OFF_W1LO);
        for (int i = tid; i < 544;  i += 256) d[i] = s[i];
        s = (const uint4*)g_w2hi[layer]; d = (uint4*)(smem + OFF_W2HI);
        for (int i = tid; i < 2176; i += 256) d[i] = s[i];
        s = (const uint4*)g_w2lo[layer]; d = (uint4*)(smem + OFF_W2LO);
        for (int i = tid; i < 2176; i += 256) d[i] = s[i];
    }
    float* sPf  = (float*)(smem + OFF_P);
    float* sB2f = (float*)(smem + OFF_B2);
    int*   sAdj = (int*)(smem + OFF_ADJ);
    if (tid < H_) { sPf[tid] = Pg[(size_t)bi*H_ + tid]; sB2f[tid] = b2[tid]; }
    sAdj[tid] = adj[(size_t)bi*V_ + tid];

    float rmax[32];
    #pragma unroll
    for (int i = 0; i < 32; ++i) rmax[i] = -1e9f;

    for (int chunk = 0; chunk < 2; ++chunk) {
        const int jbase = chunk * 128;
        __syncthreads();
        // ---- stage E chunk -> hi/lo bf16 tiles (stride ST_E2) ----
        for (int idx = tid; idx < 1024; idx += 256) {
            int j = idx >> 3, kq = idx & 7;
            float4 e4 = *(const float4*)(E + (((size_t)bi*V_) + jbase + j)*KE_ + kq*4);
            unsigned short h0=bf16b(e4.x), h1=bf16b(e4.y), h2=bf16b(e4.z), h3=bf16b(e4.w);
            uint2 hp, lp;
            hp.x = (uint32_t)h0 | ((uint32_t)h1 << 16);
            hp.y = (uint32_t)h2 | ((uint32_t)h3 << 16);
            lp.x = (uint32_t)bf16b(e4.x-bf16f(h0)) | ((uint32_t)bf16b(e4.y-bf16f(h1)) << 16);
            lp.y = (uint32_t)bf16b(e4.z-bf16f(h2)) | ((uint32_t)bf16b(e4.w-bf16f(h3)) << 16);
            uint32_t o = (uint32_t)(j*ST_E2 + kq*4) * 2u;
            *(uint2*)(smem + OFF_EHI + o) = hp;
            *(uint2*)(smem + OFF_ELO + o) = lp;
        }
        __syncthreads();

        float acc[16][4];
        #pragma unroll
        for (int n = 0; n < 16; ++n)
            #pragma unroll
            for (int p = 0; p < 4; ++p) acc[n][p] = 0.f;

        // ---- phase 1: E @ W1c (K=32) ----
        #pragma unroll
        for (int ks = 0; ks < 2; ++ks) {
            const int k0 = ks * 16;
            uint32_t aH[4], aL[4];
            uint32_t ao = (uint32_t)((j0 + rowsel)*ST_E2 + k0 + colsel) * 2u;
            ldsm4(aH, sb + OFF_EHI + ao);
            ldsm4(aL, sb + OFF_ELO + ao);
            const uint32_t brow = (uint32_t)((k0 + rowsel)*ST_W + colsel) * 2u;
            #pragma unroll
            for (int ntp = 0; ntp < 8; ++ntp) {
                uint32_t bo = brow + (uint32_t)(ntp*16*2);
                uint32_t bH[4], bL[4];
                ldsm4t(bH, sb + OFF_W1HI + bo);
                ldsm4t(bL, sb + OFF_W1LO + bo);
                mma_bf16(acc[2*ntp],   aH, &bH[0]);
                mma_bf16(acc[2*ntp+1], aH, &bH[2]);
                mma_bf16(acc[2*ntp],   aH, &bL[0]);
                mma_bf16(acc[2*ntp+1], aH, &bL[2]);
                mma_bf16(acc[2*ntp],   aL, &bH[0]);
                mma_bf16(acc[2*ntp+1], aL, &bH[2]);
            }
        }

        // ---- epilogue 1: T = relu(P + Q + D) -> A-fragments IN REGISTERS ----
        // D-fragment (g, 2tg | g+8 | +8-col) is exactly the A-fragment layout
        // for m16n8k16 k-block ks: a0..a3 <- (acc[2ks], acc[2ks+1]).
        uint32_t aH2[8][4], aL2[8][4];
        {
            const float* qA = Qg + ((size_t)(b*V_ + jbase + j0 + g))*H_;
            const float* qB = qA + 8*H_;
            #pragma unroll
            for (int ks = 0; ks < 8; ++ks) {
                #pragma unroll
                for (int h = 0; h < 2; ++h) {
                    const int nt = 2*ks + h;
                    const int c = nt*8 + tg*2;
                    float2 q0 = *(const float2*)(qA + c);
                    float2 q1 = *(const float2*)(qB + c);
                    float pc0 = sPf[c], pc1 = sPf[c+1];
                    float t0 = fmaxf(acc[nt][0] + pc0 + q0.x, 0.f);
                    float t1 = fmaxf(acc[nt][1] + pc1 + q0.y, 0.f);
                    float t2 = fmaxf(acc[nt][2] + pc0 + q1.x, 0.f);
                    float t3 = fmaxf(acc[nt][3] + pc1 + q1.y, 0.f);
                    unsigned short h0=bf16b(t0), h1=bf16b(t1), h2=bf16b(t2), h3=bf16b(t3);
                    aH2[ks][0 + 2*h] = (uint32_t)h0 | ((uint32_t)h1 << 16);
                    aH2[ks][1 + 2*h] = (uint32_t)h2 | ((uint32_t)h3 << 16);
                    aL2[ks][0 + 2*h] =
                        (uint32_t)bf16b(t0-bf16f(h0)) | ((uint32_t)bf16b(t1-bf16f(h1)) << 16);
                    aL2[ks][1 + 2*h] =
                        (uint32_t)bf16b(t2-bf16f(h2)) | ((uint32_t)bf16b(t3-bf16f(h3)) << 16);
                }
            }
        }

        #pragma unroll
        for (int n = 0; n < 16; ++n)
            #pragma unroll
            for (int p = 0; p < 4; ++p) acc[n][p] = 0.f;

        // ---- phase 2: T @ W2 (K=128), A from registers, B via ldsm ----
        #pragma unroll
        for (int ks = 0; ks < 8; ++ks) {
            const uint32_t brow = (uint32_t)((ks*16 + rowsel)*ST_W + colsel) * 2u;
            #pragma unroll
            for (int ntp = 0; ntp < 8; ++ntp) {
                uint32_t bo = brow + (uint32_t)(ntp*16*2);
                uint32_t bH[4], bL[4];
                ldsm4t(bH, sb + OFF_W2HI + bo);
                ldsm4t(bL, sb + OFF_W2LO + bo);
                mma_bf16(acc[2*ntp],   aH2[ks], &bH[0]);
                mma_bf16(acc[2*ntp+1], aH2[ks], &bH[2]);
                mma_bf16(acc[2*ntp],   aH2[ks], &bL[0]);
                mma_bf16(acc[2*ntp+1], aH2[ks], &bL[2]);
                mma_bf16(acc[2*ntp],   aL2[ks], &bH[0]);
                mma_bf16(acc[2*ntp+1], aL2[ks], &bH[2]);
            }
        }

        // ---- epilogue 2: relu(+b2), adjacency-masked col-max ----
        {
            const bool actA = sAdj[jbase + j0 + g] > 0;
            const bool actB = sAdj[jbase + j0 + 8 + g] > 0;
            #pragma unroll
            for (int nt = 0; nt < 16; ++nt) {
                const int c = nt*8 + tg*2;
                float b0 = sB2f[c], b1 = sB2f[c+1];
                if (actA) {
                    rmax[2*nt]   = fmaxf(rmax[2*nt],   fmaxf(acc[nt][0]+b0, 0.f));
                    rmax[2*nt+1] = fmaxf(rmax[2*nt+1], fmaxf(acc[nt][1]+b1, 0.f));
                }
                if (actB) {
                    rmax[2*nt]   = fmaxf(rmax[2*nt],   fmaxf(acc[nt][2]+b0, 0.f));
                    rmax[2*nt+1] = fmaxf(rmax[2*nt+1], fmaxf(acc[nt][3]+b1, 0.f));
                }
            }
        }
    }

    // reduce over g (lanes differing in bits 2..4), then over warps via smem
    #pragma unroll
    for (int off = 4; off <= 16; off <<= 1)
        #pragma unroll
        for (int i = 0; i < 32; ++i)
            rmax[i] = fmaxf(rmax[i], __shfl_xor_sync(0xffffffffu, rmax[i], off));

    float* red = (float*)(smem + OFF_RED);
    if (lane < 4) {
        #pragma unroll
        for (int nt = 0; nt < 16; ++nt) {
            red[w*H_ + nt*8 + lane*2]     = rmax[2*nt];
            red[w*H_ + nt*8 + lane*2 + 1] = rmax[2*nt+1];
        }
    }
    __syncthreads();
    if (tid < H_) {
        float v = red[tid];
        #pragma unroll
        for (int ww = 1; ww < 8; ++ww) v = fmaxf(v, red[ww*H_ + tid]);
        Xout[(size_t)bi*H_ + tid] = (v < -1e8f) ? 0.f : v;
    }
}

// ---------------------------------------------------------------------------
__global__ void rs_kernel(const float* __restrict__ x, const float* __restrict__ W3,
                          const float* __restrict__ b3,
                          float* __restrict__ R, float* __restrict__ S)
{
    __shared__ float sx[4][128];
    const int m = threadIdx.x;
    const int base = blockIdx.x * 4;
    if (m < 128) {
        #pragma unroll
        for (int r = 0; r < 4; ++r) sx[r][m] = x[(size_t)(base + r)*H_ + m];
    }
    __syncthreads();
    float r0=0.f,r1=0.f,r2=0.f,r3=0.f;
    float bb = b3[m];
    float s0=bb,s1=bb,s2=bb,s3=bb;
    for (int c = 0; c < 128; ++c) {
        float wa = W3[c*H2_ + m], wb = W3[(128+c)*H2_ + m];
        r0 += sx[0][c]*wa; s0 += sx[0][c]*wb;
        r1 += sx[1][c]*wa; s1 += sx[1][c]*wb;
        r2 += sx[2][c]*wa; s2 += sx[2][c]*wb;
        r3 += sx[3][c]*wa; s3 += sx[3][c]*wb;
    }
    R[(size_t)(base+0)*H2_+m]=r0; S[(size_t)(base+0)*H2_+m]=s0;
    R[(size_t)(base+1)*H2_+m]=r1; S[(size_t)(base+1)*H2_+m]=s1;
    R[(size_t)(base+2)*H2_+m]=r2; S[(size_t)(base+2)*H2_+m]=s2;
    R[(size_t)(base+3)*H2_+m]=r3; S[(size_t)(base+3)*H2_+m]=s3;
}

#define IL_ 8
#define MC_ 32
__global__ void __launch_bounds__(256)
pair_kernel(const float* __restrict__ R, const float* __restrict__ S,
            const float* __restrict__ outW, const float* __restrict__ outB,
            float* __restrict__ out)
{
    __shared__ float sR[V_][MC_+1];
    __shared__ float sS[IL_][MC_+1];
    __shared__ float sw[MC_];
    const int tid = threadIdx.x;
    const int b = blockIdx.y, i0 = blockIdx.x * IL_;
    float acc[IL_];
    #pragma unroll
    for (int il = 0; il < IL_; ++il) acc[il] = 0.f;

    for (int mc = 0; mc < H2_; mc += MC_) {
        __syncthreads();
        #pragma unroll 4
        for (int idx = tid; idx < V_*MC_; idx += 256) {
            int j = idx >> 5, mm = idx & (MC_-1);
            sR[j][mm] = R[((size_t)b*V_ + j)*H2_ + mc + mm];
        }
        if (tid < IL_*MC_) {
            int il = tid >> 5, mm = tid & (MC_-1);
            sS[il][mm] = S[((size_t)b*V_ + i0 + il)*H2_ + mc + mm];
        }
        if (tid < MC_) sw[tid] = outW[mc + tid];
        __syncthreads();
        #pragma unroll
        for (int il = 0; il < IL_; ++il) {
            float a = 0.f;
            #pragma unroll
            for (int mm = 0; mm < MC_; ++mm)
                a += fmaxf(sR[tid][mm] + sS[il][mm], 0.f) * sw[mm];
            acc[il] += a;
        }
    }
    const float ob = outB[0];
    #pragma unroll
    for (int il = 0; il < IL_; ++il) {
        float z = acc[il] + ob;
        out[((size_t)b*V_ + i0 + il)*V_ + tid] = 1.f / (1.f + expf(-z));
    }
}

// ---------------------------------------------------------------------------
extern "C" void kernel_launch(void* const* d_in, const int* in_sizes, int n_in,
                              void* d_out, int out_size)
{
    const int*   adj   = (const int*)  d_in[0];
    const float* x0    = (const float*)d_in[1];
    const float* e     = (const float*)d_in[2];
    const float* ec1W1 = (const float*)d_in[3];
    const float* ec1b1 = (const float*)d_in[4];
    const float* ec1W2 = (const float*)d_in[5];
    const float* ec1b2 = (const float*)d_in[6];
    const float* ec2W1 = (const float*)d_in[7];
    const float* ec2b1 = (const float*)d_in[8];
    const float* ec2W2 = (const float*)d_in[9];
    const float* ec2b2 = (const float*)d_in[10];
    const float* h3W   = (const float*)d_in[11];
    const float* h3b   = (const float*)d_in[12];
    const float* outW  = (const float*)d_in[13];
    const float* outB  = (const float*)d_in[14];
    float* out = (float*)d_out;

    float *P, *Q, *X1, *X2, *R, *S;
    cudaGetSymbolAddress((void**)&P,  g_P);
    cudaGetSymbolAddress((void**)&Q,  g_Q);
    cudaGetSymbolAddress((void**)&X1, g_X1);
    cudaGetSymbolAddress((void**)&X2, g_X2);
    cudaGetSymbolAddress((void**)&R,  g_R);
    cudaGetSymbolAddress((void**)&S,  g_S);
    unsigned short *w1h0,*w1l0,*w2h0,*w2l0;
    cudaGetSymbolAddress((void**)&w1h0, g_w1hi);
    cudaGetSymbolAddress((void**)&w1l0, g_w1lo);
    cudaGetSymbolAddress((void**)&w2h0, g_w2hi);
    cudaGetSymbolAddress((void**)&w2l0, g_w2lo);

    cudaFuncSetAttribute(ec_hmma, cudaFuncAttributeMaxDynamicSharedMemorySize, SMEM_EC);

    const int PREP_N = (KE_*H_ + H_*H_ + 255) / 256;
    prep_w<<<PREP_N, 256>>>(ec1W1, 64,  ec1W2, w1h0, w1l0, w2h0, w2l0);
    prep_w<<<PREP_N, 256>>>(ec2W1, 128, ec2W2,
                            w1h0 + KE_*ST_W, w1l0 + KE_*ST_W,
                            w2h0 + H_*ST_W,  w2l0 + H_*ST_W);

    pq_kernel<<<B_*V_/4, 128>>>(x0, ec1W1, ec1b1, 64, P, Q);
    ec_hmma<<<B_*V_, 256, SMEM_EC>>>(P, Q, e, ec1b2, adj, X1, 0);

    pq_kernel<<<B_*V_/4, 128>>>(X1, ec2W1, ec2b1, 128, P, Q);
    ec_hmma<<<B_*V_, 256, SMEM_EC>>>(P, Q, e, ec2b2, adj, X2, 1);

    rs_kernel<<<B_*V_/4, 256>>>(X2, h3W, h3b, R, S);
    dim3 pg(V_/IL_, B_);
    pair_kernel<<<pg, 256>>>(R, S, outW, outB, out);
}

// round 7
// speedup vs baseline: 2.0740x; 1.2249x over previous
#include <cuda_runtime.h>
#include <cuda_bf16.h>
#include <cstdint>

#define B_   4
#define V_   256
#define H_   128
#define KE_  32
#define H2_  256
#define ST_W 136    // bf16 row stride for W tiles (272B, ldmatrix conflict-free)
#define ST_E2 40    // bf16 row stride for E tiles (80B)
#define NBI  (B_*V_)
#define ETILE 10240         // shorts per (bi) E tile: 256*ST_E2
#define EBYTES 20480        // bytes per (bi) E tile (one of hi/lo)

__device__ float g_P [NBI*H_];
__device__ float g_Q [NBI*H_];
__device__ float g_X1[NBI*H_];
__device__ float g_X2[NBI*H_];
__device__ float g_R [NBI*H2_];
__device__ float g_S [NBI*H2_];
__device__ __align__(16) unsigned short g_w1hi[2][KE_*ST_W];
__device__ __align__(16) unsigned short g_w1lo[2][KE_*ST_W];
__device__ __align__(16) unsigned short g_w2hi[2][H_*ST_W];
__device__ __align__(16) unsigned short g_w2lo[2][H_*ST_W];
// pre-converted E tiles (shared by both ec layers): [bi][256 rows * ST_E2]
__device__ __align__(16) unsigned short g_Ehi[NBI][ETILE];
__device__ __align__(16) unsigned short g_Elo[NBI][ETILE];

__device__ __forceinline__ unsigned short bf16b(float f) {
    __nv_bfloat16 h = __float2bfloat16(f);
    return *(unsigned short*)&h;
}
__device__ __forceinline__ float bf16f(unsigned short u) {
    __nv_bfloat16 h = *(__nv_bfloat16*)&u;
    return __bfloat162float(h);
}
__device__ __forceinline__ uint32_t smem_to_u32(const void* p) {
    uint32_t a;
    asm("{ .reg .u64 t; cvta.to.shared.u64 t, %1; cvt.u32.u64 %0, t; }" : "=r"(a) : "l"(p));
    return a;
}
__device__ __forceinline__ void ldsm4(uint32_t* r, uint32_t a) {
    asm volatile("ldmatrix.sync.aligned.m8n8.x4.shared.b16 {%0,%1,%2,%3}, [%4];"
        : "=r"(r[0]), "=r"(r[1]), "=r"(r[2]), "=r"(r[3]) : "r"(a));
}
__device__ __forceinline__ void ldsm4t(uint32_t* r, uint32_t a) {
    asm volatile("ldmatrix.sync.aligned.m8n8.x4.trans.shared.b16 {%0,%1,%2,%3}, [%4];"
        : "=r"(r[0]), "=r"(r[1]), "=r"(r[2]), "=r"(r[3]) : "r"(a));
}
__device__ __forceinline__ void mma_bf16(float* c, const uint32_t* a, const uint32_t* b) {
    asm volatile("mma.sync.aligned.m16n8k16.row.col.f32.bf16.bf16.f32 "
        "{%0,%1,%2,%3}, {%4,%5,%6,%7}, {%8,%9}, {%0,%1,%2,%3};"
        : "+f"(c[0]), "+f"(c[1]), "+f"(c[2]), "+f"(c[3])
        : "r"(a[0]), "r"(a[1]), "r"(a[2]), "r"(a[3]), "r"(b[0]), "r"(b[1]));
}
__device__ __forceinline__ void cp16(uint32_t dst, const void* src) {
    asm volatile("cp.async.cg.shared.global [%0], [%1], 16;" :: "r"(dst), "l"(src));
}
#define CP_COMMIT() asm volatile("cp.async.commit_group;" ::: "memory")
#define CP_WAIT1()  asm volatile("cp.async.wait_group 1;" ::: "memory")
#define CP_WAIT0()  asm volatile("cp.async.wait_group 0;" ::: "memory")

// SMEM byte offsets
#define OFF_B2    0
#define OFF_P     512
#define OFF_ADJ   1024
#define OFF_RED   2048
#define OFF_W1HI  6144
#define OFF_W1LO  14848
#define OFF_W2HI  23552
#define OFF_W2LO  58368
#define OFF_E0    93184              // two buffers of (hi 20480 + lo 20480)
#define EBUF_SZ   (2*EBYTES)
#define SMEM_EC   (OFF_E0 + 2*EBUF_SZ)   // 175104

// ---------------------------------------------------------------------------
__global__ void prep_w(const float* __restrict__ W1, int C, const float* __restrict__ W2,
                       unsigned short* __restrict__ w1h, unsigned short* __restrict__ w1l,
                       unsigned short* __restrict__ w2h, unsigned short* __restrict__ w2l)
{
    int idx = blockIdx.x * blockDim.x + threadIdx.x;
    if (idx < KE_*H_) {
        int k = idx >> 7, c = idx & 127;
        float w = W1[(size_t)(2*C + k)*H_ + c];
        unsigned short h = bf16b(w);
        w1h[k*ST_W + c] = h;  w1l[k*ST_W + c] = bf16b(w - bf16f(h));
    } else if (idx < KE_*H_ + H_*H_) {
        int t = idx - KE_*H_;
        int k = t >> 7, c = t & 127;
        float w = W2[(size_t)k*H_ + c];
        unsigned short h = bf16b(w);
        w2h[k*ST_W + c] = h;  w2l[k*ST_W + c] = bf16b(w - bf16f(h));
    }
}

// E -> bf16 hi/lo tiles, once per problem (both ec layers share it)
__global__ void prep_e(const float* __restrict__ E)
{
    const int bi = blockIdx.x;
    const int tid = threadIdx.x;
    unsigned short* eh = g_Ehi[bi];
    unsigned short* el = g_Elo[bi];
    for (int idx = tid; idx < 2048; idx += 256) {
        int j = idx >> 3, kq = idx & 7;
        float4 e4 = *(const float4*)(E + ((size_t)bi*V_ + j)*KE_ + kq*4);
        unsigned short h0=bf16b(e4.x), h1=bf16b(e4.y), h2=bf16b(e4.z), h3=bf16b(e4.w);
        uint2 hp, lp;
        hp.x = (uint32_t)h0 | ((uint32_t)h1 << 16);
        hp.y = (uint32_t)h2 | ((uint32_t)h3 << 16);
        lp.x = (uint32_t)bf16b(e4.x-bf16f(h0)) | ((uint32_t)bf16b(e4.y-bf16f(h1)) << 16);
        lp.y = (uint32_t)bf16b(e4.z-bf16f(h2)) | ((uint32_t)bf16b(e4.w-bf16f(h3)) << 16);
        int o = j*ST_E2 + kq*4;
        *(uint2*)(eh + o) = hp;
        *(uint2*)(el + o) = lp;
    }
}

// ---------------------------------------------------------------------------
__global__ void pq_kernel(const float* __restrict__ x, const float* __restrict__ W1,
                          const float* __restrict__ b1, int C_in,
                          float* __restrict__ P, float* __restrict__ Q)
{
    __shared__ float sx[4][128];
    const int h = threadIdx.x;
    const int base = blockIdx.x * 4;
    #pragma unroll
    for (int r = 0; r < 4; ++r)
        if (h < C_in) sx[r][h] = x[(size_t)(base + r) * C_in + h];
    __syncthreads();
    float bb = b1[h];
    float p0=bb,p1=bb,p2=bb,p3=bb, q0=0.f,q1=0.f,q2=0.f,q3=0.f;
    for (int c = 0; c < C_in; ++c) {
        float wa = W1[c*H_ + h], wb = W1[(C_in+c)*H_ + h], wd = wa - wb;
        p0 += sx[0][c]*wd; q0 += sx[0][c]*wb;
        p1 += sx[1][c]*wd; q1 += sx[1][c]*wb;
        p2 += sx[2][c]*wd; q2 += sx[2][c]*wb;
        p3 += sx[3][c]*wd; q3 += sx[3][c]*wb;
    }
    P[(size_t)(base+0)*H_+h]=p0; Q[(size_t)(base+0)*H_+h]=q0;
    P[(size_t)(base+1)*H_+h]=p1; Q[(size_t)(base+1)*H_+h]=q1;
    P[(size_t)(base+2)*H_+h]=p2; Q[(size_t)(base+2)*H_+h]=q2;
    P[(size_t)(base+3)*H_+h]=p3; Q[(size_t)(base+3)*H_+h]=q3;
}

// ---------------------------------------------------------------------------
// Persistent-CTA fused EdgeConv on HMMA. grid = #SMs; each CTA loops over bi.
// Weights staged once; E tiles double-buffered via cp.async.
// ---------------------------------------------------------------------------
__global__ void __launch_bounds__(256, 1)
ec_hmma(const float* __restrict__ Pg, const float* __restrict__ Qg,
        const float* __restrict__ b2, const int* __restrict__ adj,
        float* __restrict__ Xout, int layer)
{
    extern __shared__ char smem[];
    const uint32_t sb = smem_to_u32(smem);
    const int tid = threadIdx.x, w = tid >> 5, lane = tid & 31;
    const int g = lane >> 2, tg = lane & 3;
    const int j0 = w * 16;
    const int rowsel = lane & 15, colsel = (lane >> 4) * 8;

    {   // stage weight tiles ONCE
        const uint4* s; uint4* d;
        s = (const uint4*)g_w1hi[layer]; d = (uint4*)(smem + OFF_W1HI);
        for (int i = tid; i < 544;  i += 256) d[i] = s[i];
        s = (const uint4*)g_w1lo[layer]; d = (uint4*)(smem + OFF_W1LO);
        for (int i = tid; i < 544;  i += 256) d[i] = s[i];
        s = (const uint4*)g_w2hi[layer]; d = (uint4*)(smem + OFF_W2HI);
        for (int i = tid; i < 2176; i += 256) d[i] = s[i];
        s = (const uint4*)g_w2lo[layer]; d = (uint4*)(smem + OFF_W2LO);
        for (int i = tid; i < 2176; i += 256) d[i] = s[i];
    }
    float* sPf  = (float*)(smem + OFF_P);
    float* sB2f = (float*)(smem + OFF_B2);
    int*   sAdj = (int*)(smem + OFF_ADJ);
    float* red  = (float*)(smem + OFF_RED);
    if (tid < H_) sB2f[tid] = b2[tid];

    // prefetch first E tile into buffer 0
    int cur = 0;
    {
        const char* sh = (const char*)g_Ehi[blockIdx.x];
        const char* sl = (const char*)g_Elo[blockIdx.x];
        for (int i = tid; i < EBYTES/16; i += 256) {
            cp16(sb + OFF_E0 + i*16,          sh + i*16);
            cp16(sb + OFF_E0 + EBYTES + i*16, sl + i*16);
        }
        CP_COMMIT();
    }

    for (int bi = blockIdx.x; bi < NBI; bi += gridDim.x) {
        const int b = bi >> 8;
        const int nbi = bi + gridDim.x;
        if (nbi < NBI) {   // prefetch next E tile into other buffer
            const int nb = 1 - cur;
            const char* sh = (const char*)g_Ehi[nbi];
            const char* sl = (const char*)g_Elo[nbi];
            for (int i = tid; i < EBYTES/16; i += 256) {
                cp16(sb + OFF_E0 + nb*EBUF_SZ + i*16,          sh + i*16);
                cp16(sb + OFF_E0 + nb*EBUF_SZ + EBYTES + i*16, sl + i*16);
            }
            CP_COMMIT();
            CP_WAIT1();
        } else {
            CP_WAIT0();
        }
        if (tid < H_) sPf[tid] = Pg[(size_t)bi*H_ + tid];
        sAdj[tid] = adj[(size_t)bi*V_ + tid];
        __syncthreads();

        const uint32_t eH = sb + OFF_E0 + cur*EBUF_SZ;
        const uint32_t eL = eH + EBYTES;

        float rmax[32];
        #pragma unroll
        for (int i = 0; i < 32; ++i) rmax[i] = -1e9f;

        #pragma unroll
        for (int chunk = 0; chunk < 2; ++chunk) {
            const int jbase = chunk * 128;

            float acc[16][4];
            #pragma unroll
            for (int n = 0; n < 16; ++n)
                #pragma unroll
                for (int p = 0; p < 4; ++p) acc[n][p] = 0.f;

            // ---- phase 1: E @ W1c (K=32) ----
            #pragma unroll
            for (int ks = 0; ks < 2; ++ks) {
                const int k0 = ks * 16;
                uint32_t aH[4], aL[4];
                uint32_t ao = (uint32_t)((jbase + j0 + rowsel)*ST_E2 + k0 + colsel) * 2u;
                ldsm4(aH, eH + ao);
                ldsm4(aL, eL + ao);
                const uint32_t brow = (uint32_t)((k0 + rowsel)*ST_W + colsel) * 2u;
                #pragma unroll
                for (int ntp = 0; ntp < 8; ++ntp) {
                    uint32_t bo = brow + (uint32_t)(ntp*16*2);
                    uint32_t bH[4], bL[4];
                    ldsm4t(bH, sb + OFF_W1HI + bo);
                    ldsm4t(bL, sb + OFF_W1LO + bo);
                    mma_bf16(acc[2*ntp],   aH, &bH[0]);
                    mma_bf16(acc[2*ntp+1], aH, &bH[2]);
                    mma_bf16(acc[2*ntp],   aH, &bL[0]);
                    mma_bf16(acc[2*ntp+1], aH, &bL[2]);
                    mma_bf16(acc[2*ntp],   aL, &bH[0]);
                    mma_bf16(acc[2*ntp+1], aL, &bH[2]);
                }
            }

            // ---- epilogue 1: T = relu(P + Q + D) -> A-fragments in registers ----
            uint32_t aH2[8][4], aL2[8][4];
            {
                const float* qA = Qg + ((size_t)(b*V_ + jbase + j0 + g))*H_;
                const float* qB = qA + 8*H_;
                #pragma unroll
                for (int ks = 0; ks < 8; ++ks) {
                    #pragma unroll
                    for (int h = 0; h < 2; ++h) {
                        const int nt = 2*ks + h;
                        const int c = nt*8 + tg*2;
                        float2 q0 = *(const float2*)(qA + c);
                        float2 q1 = *(const float2*)(qB + c);
                        float pc0 = sPf[c], pc1 = sPf[c+1];
                        float t0 = fmaxf(acc[nt][0] + pc0 + q0.x, 0.f);
                        float t1 = fmaxf(acc[nt][1] + pc1 + q0.y, 0.f);
                        float t2 = fmaxf(acc[nt][2] + pc0 + q1.x, 0.f);
                        float t3 = fmaxf(acc[nt][3] + pc1 + q1.y, 0.f);
                        unsigned short h0=bf16b(t0), h1=bf16b(t1), h2=bf16b(t2), h3=bf16b(t3);
                        aH2[ks][0 + 2*h] = (uint32_t)h0 | ((uint32_t)h1 << 16);
                        aH2[ks][1 + 2*h] = (uint32_t)h2 | ((uint32_t)h3 << 16);
                        aL2[ks][0 + 2*h] =
                            (uint32_t)bf16b(t0-bf16f(h0)) | ((uint32_t)bf16b(t1-bf16f(h1)) << 16);
                        aL2[ks][1 + 2*h] =
                            (uint32_t)bf16b(t2-bf16f(h2)) | ((uint32_t)bf16b(t3-bf16f(h3)) << 16);
                    }
                }
            }

            #pragma unroll
            for (int n = 0; n < 16; ++n)
                #pragma unroll
                for (int p = 0; p < 4; ++p) acc[n][p] = 0.f;

            // ---- phase 2: T @ W2 (K=128), A from registers ----
            #pragma unroll
            for (int ks = 0; ks < 8; ++ks) {
                const uint32_t brow = (uint32_t)((ks*16 + rowsel)*ST_W + colsel) * 2u;
                #pragma unroll
                for (int ntp = 0; ntp < 8; ++ntp) {
                    uint32_t bo = brow + (uint32_t)(ntp*16*2);
                    uint32_t bH[4], bL[4];
                    ldsm4t(bH, sb + OFF_W2HI + bo);
                    ldsm4t(bL, sb + OFF_W2LO + bo);
                    mma_bf16(acc[2*ntp],   aH2[ks], &bH[0]);
                    mma_bf16(acc[2*ntp+1], aH2[ks], &bH[2]);
                    mma_bf16(acc[2*ntp],   aH2[ks], &bL[0]);
                    mma_bf16(acc[2*ntp+1], aH2[ks], &bL[2]);
                    mma_bf16(acc[2*ntp],   aL2[ks], &bH[0]);
                    mma_bf16(acc[2*ntp+1], aL2[ks], &bH[2]);
                }
            }

            // ---- epilogue 2: relu(+b2), adjacency-masked col-max ----
            {
                const bool actA = sAdj[jbase + j0 + g] > 0;
                const bool actB = sAdj[jbase + j0 + 8 + g] > 0;
                #pragma unroll
                for (int nt = 0; nt < 16; ++nt) {
                    const int c = nt*8 + tg*2;
                    float b0 = sB2f[c], b1 = sB2f[c+1];
                    if (actA) {
                        rmax[2*nt]   = fmaxf(rmax[2*nt],   fmaxf(acc[nt][0]+b0, 0.f));
                        rmax[2*nt+1] = fmaxf(rmax[2*nt+1], fmaxf(acc[nt][1]+b1, 0.f));
                    }
                    if (actB) {
                        rmax[2*nt]   = fmaxf(rmax[2*nt],   fmaxf(acc[nt][2]+b0, 0.f));
                        rmax[2*nt+1] = fmaxf(rmax[2*nt+1], fmaxf(acc[nt][3]+b1, 0.f));
                    }
                }
            }
        }

        // reduce over g (lane bits 2..4), then over warps via smem
        #pragma unroll
        for (int off = 4; off <= 16; off <<= 1)
            #pragma unroll
            for (int i = 0; i < 32; ++i)
                rmax[i] = fmaxf(rmax[i], __shfl_xor_sync(0xffffffffu, rmax[i], off));

        if (lane < 4) {
            #pragma unroll
            for (int nt = 0; nt < 16; ++nt) {
                red[w*H_ + nt*8 + lane*2]     = rmax[2*nt];
                red[w*H_ + nt*8 + lane*2 + 1] = rmax[2*nt+1];
            }
        }
        __syncthreads();
        if (tid < H_) {
            float v = red[tid];
            #pragma unroll
            for (int ww = 1; ww < 8; ++ww) v = fmaxf(v, red[ww*H_ + tid]);
            Xout[(size_t)bi*H_ + tid] = (v < -1e8f) ? 0.f : v;
        }
        __syncthreads();   // guard red + E-buffer reuse before next iteration
        cur ^= 1;
    }
}

// ---------------------------------------------------------------------------
__global__ void rs_kernel(const float* __restrict__ x, const float* __restrict__ W3,
                          const float* __restrict__ b3,
                          float* __restrict__ R, float* __restrict__ S)
{
    __shared__ float sx[4][128];
    const int m = threadIdx.x;
    const int base = blockIdx.x * 4;
    if (m < 128) {
        #pragma unroll
        for (int r = 0; r < 4; ++r) sx[r][m] = x[(size_t)(base + r)*H_ + m];
    }
    __syncthreads();
    float r0=0.f,r1=0.f,r2=0.f,r3=0.f;
    float bb = b3[m];
    float s0=bb,s1=bb,s2=bb,s3=bb;
    for (int c = 0; c < 128; ++c) {
        float wa = W3[c*H2_ + m], wb = W3[(128+c)*H2_ + m];
        r0 += sx[0][c]*wa; s0 += sx[0][c]*wb;
        r1 += sx[1][c]*wa; s1 += sx[1][c]*wb;
        r2 += sx[2][c]*wa; s2 += sx[2][c]*wb;
        r3 += sx[3][c]*wa; s3 += sx[3][c]*wb;
    }
    R[(size_t)(base+0)*H2_+m]=r0; S[(size_t)(base+0)*H2_+m]=s0;
    R[(size_t)(base+1)*H2_+m]=r1; S[(size_t)(base+1)*H2_+m]=s1;
    R[(size_t)(base+2)*H2_+m]=r2; S[(size_t)(base+2)*H2_+m]=s2;
    R[(size_t)(base+3)*H2_+m]=r3; S[(size_t)(base+3)*H2_+m]=s3;
}

#define IL_ 8
#define MC_ 32
__global__ void __launch_bounds__(256)
pair_kernel(const float* __restrict__ R, const float* __restrict__ S,
            const float* __restrict__ outW, const float* __restrict__ outB,
            float* __restrict__ out)
{
    __shared__ float sR[V_][MC_+1];
    __shared__ float sS[IL_][MC_+1];
    __shared__ float sw[MC_];
    const int tid = threadIdx.x;
    const int b = blockIdx.y, i0 = blockIdx.x * IL_;
    float acc[IL_];
    #pragma unroll
    for (int il = 0; il < IL_; ++il) acc[il] = 0.f;

    for (int mc = 0; mc < H2_; mc += MC_) {
        __syncthreads();
        #pragma unroll 4
        for (int idx = tid; idx < V_*MC_; idx += 256) {
            int j = idx >> 5, mm = idx & (MC_-1);
            sR[j][mm] = R[((size_t)b*V_ + j)*H2_ + mc + mm];
        }
        if (tid < IL_*MC_) {
            int il = tid >> 5, mm = tid & (MC_-1);
            sS[il][mm] = S[((size_t)b*V_ + i0 + il)*H2_ + mc + mm];
        }
        if (tid < MC_) sw[tid] = outW[mc + tid];
        __syncthreads();
        #pragma unroll
        for (int il = 0; il < IL_; ++il) {
            float a = 0.f;
            #pragma unroll
            for (int mm = 0; mm < MC_; ++mm)
                a += fmaxf(sR[tid][mm] + sS[il][mm], 0.f) * sw[mm];
            acc[il] += a;
        }
    }
    const float ob = outB[0];
    #pragma unroll
    for (int il = 0; il < IL_; ++il) {
        float z = acc[il] + ob;
        out[((size_t)b*V_ + i0 + il)*V_ + tid] = 1.f / (1.f + expf(-z));
    }
}

// ---------------------------------------------------------------------------
extern "C" void kernel_launch(void* const* d_in, const int* in_sizes, int n_in,
                              void* d_out, int out_size)
{
    const int*   adj   = (const int*)  d_in[0];
    const float* x0    = (const float*)d_in[1];
    const float* e     = (const float*)d_in[2];
    const float* ec1W1 = (const float*)d_in[3];
    const float* ec1b1 = (const float*)d_in[4];
    const float* ec1W2 = (const float*)d_in[5];
    const float* ec1b2 = (const float*)d_in[6];
    const float* ec2W1 = (const float*)d_in[7];
    const float* ec2b1 = (const float*)d_in[8];
    const float* ec2W2 = (const float*)d_in[9];
    const float* ec2b2 = (const float*)d_in[10];
    const float* h3W   = (const float*)d_in[11];
    const float* h3b   = (const float*)d_in[12];
    const float* outW  = (const float*)d_in[13];
    const float* outB  = (const float*)d_in[14];
    float* out = (float*)d_out;

    float *P, *Q, *X1, *X2, *R, *S;
    cudaGetSymbolAddress((void**)&P,  g_P);
    cudaGetSymbolAddress((void**)&Q,  g_Q);
    cudaGetSymbolAddress((void**)&X1, g_X1);
    cudaGetSymbolAddress((void**)&X2, g_X2);
    cudaGetSymbolAddress((void**)&R,  g_R);
    cudaGetSymbolAddress((void**)&S,  g_S);
    unsigned short *w1h0,*w1l0,*w2h0,*w2l0;
    cudaGetSymbolAddress((void**)&w1h0, g_w1hi);
    cudaGetSymbolAddress((void**)&w1l0, g_w1lo);
    cudaGetSymbolAddress((void**)&w2h0, g_w2hi);
    cudaGetSymbolAddress((void**)&w2l0, g_w2lo);

    cudaFuncSetAttribute(ec_hmma, cudaFuncAttributeMaxDynamicSharedMemorySize, SMEM_EC);

    int sms = 148;
    cudaDeviceGetAttribute(&sms, cudaDevAttrMultiProcessorCount, 0);
    int grid = sms < NBI ? sms : NBI;

    const int PREP_N = (KE_*H_ + H_*H_ + 255) / 256;
    prep_w<<<PREP_N, 256>>>(ec1W1, 64,  ec1W2, w1h0, w1l0, w2h0, w2l0);
    prep_w<<<PREP_N, 256>>>(ec2W1, 128, ec2W2,
                            w1h0 + KE_*ST_W, w1l0 + KE_*ST_W,
                            w2h0 + H_*ST_W,  w2l0 + H_*ST_W);
    prep_e<<<NBI, 256>>>(e);

    pq_kernel<<<NBI/4, 128>>>(x0, ec1W1, ec1b1, 64, P, Q);
    ec_hmma<<<grid, 256, SMEM_EC>>>(P, Q, ec1b2, adj, X1, 0);

    pq_kernel<<<NBI/4, 128>>>(X1, ec2W1, ec2b1, 128, P, Q);
    ec_hmma<<<grid, 256, SMEM_EC>>>(P, Q, ec2b2, adj, X2, 1);

    rs_kernel<<<NBI/4, 256>>>(X2, h3W, h3b, R, S);
    dim3 pg(V_/IL_, B_);
    pair_kernel<<<pg, 256>>>(R, S, outW, outB, out);
}

// round 8
// speedup vs baseline: 2.1696x; 1.0461x over previous
#include <cuda_runtime.h>
#include <cuda_bf16.h>
#include <cstdint>

#define B_   4
#define V_   256
#define H_   128
#define KE_  32
#define H2_  256
#define ST_W 136    // bf16 row stride for W tiles (272B, ldmatrix conflict-free)
#define ST_E2 40    // bf16 row stride for E tiles (80B)
#define NBI  (B_*V_)
#define ETILE 10240
#define EBYTES 20480

__device__ float g_P [NBI*H_];
__device__ float g_Q [NBI*H_];
__device__ float g_X1[NBI*H_];
__device__ float g_X2[NBI*H_];
__device__ float g_R [NBI*H2_];
__device__ float g_S [NBI*H2_];
__device__ __align__(16) unsigned short g_w1hi[2][KE_*ST_W];
__device__ __align__(16) unsigned short g_w1lo[2][KE_*ST_W];
__device__ __align__(16) unsigned short g_w2hi[2][H_*ST_W];
__device__ __align__(16) unsigned short g_w2lo[2][H_*ST_W];
__device__ __align__(16) unsigned short g_Ehi[NBI][ETILE];
__device__ __align__(16) unsigned short g_Elo[NBI][ETILE];

__device__ __forceinline__ unsigned short bf16b(float f) {
    __nv_bfloat16 h = __float2bfloat16(f);
    return *(unsigned short*)&h;
}
__device__ __forceinline__ float bf16f(unsigned short u) {
    __nv_bfloat16 h = *(__nv_bfloat16*)&u;
    return __bfloat162float(h);
}
__device__ __forceinline__ uint32_t smem_to_u32(const void* p) {
    uint32_t a;
    asm("{ .reg .u64 t; cvta.to.shared.u64 t, %1; cvt.u32.u64 %0, t; }" : "=r"(a) : "l"(p));
    return a;
}
__device__ __forceinline__ void ldsm4(uint32_t* r, uint32_t a) {
    asm volatile("ldmatrix.sync.aligned.m8n8.x4.shared.b16 {%0,%1,%2,%3}, [%4];"
        : "=r"(r[0]), "=r"(r[1]), "=r"(r[2]), "=r"(r[3]) : "r"(a));
}
__device__ __forceinline__ void ldsm4t(uint32_t* r, uint32_t a) {
    asm volatile("ldmatrix.sync.aligned.m8n8.x4.trans.shared.b16 {%0,%1,%2,%3}, [%4];"
        : "=r"(r[0]), "=r"(r[1]), "=r"(r[2]), "=r"(r[3]) : "r"(a));
}
__device__ __forceinline__ void mma_bf16(float* c, const uint32_t* a, const uint32_t* b) {
    asm volatile("mma.sync.aligned.m16n8k16.row.col.f32.bf16.bf16.f32 "
        "{%0,%1,%2,%3}, {%4,%5,%6,%7}, {%8,%9}, {%0,%1,%2,%3};"
        : "+f"(c[0]), "+f"(c[1]), "+f"(c[2]), "+f"(c[3])
        : "r"(a[0]), "r"(a[1]), "r"(a[2]), "r"(a[3]), "r"(b[0]), "r"(b[1]));
}
__device__ __forceinline__ void cp16(uint32_t dst, const void* src) {
    asm volatile("cp.async.cg.shared.global [%0], [%1], 16;" :: "r"(dst), "l"(src));
}
#define CP_COMMIT() asm volatile("cp.async.commit_group;" ::: "memory")
#define CP_WAIT1()  asm volatile("cp.async.wait_group 1;" ::: "memory")
#define CP_WAIT0()  asm volatile("cp.async.wait_group 0;" ::: "memory")

// SMEM byte offsets (ec kernel)
#define OFF_B2    0
#define OFF_P     512
#define OFF_ADJ   1024
#define OFF_RED   2048
#define OFF_W1HI  6144
#define OFF_W1LO  14848
#define OFF_W2HI  23552
#define OFF_W2LO  58368
#define OFF_E0    93184
#define EBUF_SZ   (2*EBYTES)
#define SMEM_EC   (OFF_E0 + 2*EBUF_SZ)   // 175104

// ---------------------------------------------------------------------------
// pq: P = x@(W1a-W1b)+b1, Q = x@W1b.  256 thr = (cs:2, h:128), 4 nodes/blk.
// ---------------------------------------------------------------------------
__device__ __forceinline__ void pq_impl(int group, const float* __restrict__ x,
                                        const float* __restrict__ W1,
                                        const float* __restrict__ b1, int C_in,
                                        float* __restrict__ P, float* __restrict__ Q)
{
    __shared__ float sx[4][128];
    __shared__ float sp[2][4][128], sq[2][4][128];
    const int tid = threadIdx.x;
    const int cs = tid >> 7, h = tid & 127;
    const int base = group * 4;
    const int lg = (C_in == 64) ? 6 : 7;
    for (int i = tid; i < 4*C_in; i += 256)
        sx[i >> lg][i & (C_in-1)] = x[(size_t)(base + (i >> lg))*C_in + (i & (C_in-1))];
    __syncthreads();

    const int c0 = cs * (C_in >> 1), c1 = c0 + (C_in >> 1);
    float p[4] = {0.f,0.f,0.f,0.f}, q[4] = {0.f,0.f,0.f,0.f};
    for (int c = c0; c < c1; ++c) {
        float wa = W1[c*H_ + h], wb = W1[(C_in+c)*H_ + h], wd = wa - wb;
        #pragma unroll
        for (int r = 0; r < 4; ++r) { p[r] += sx[r][c]*wd; q[r] += sx[r][c]*wb; }
    }
    #pragma unroll
    for (int r = 0; r < 4; ++r) { sp[cs][r][h] = p[r]; sq[cs][r][h] = q[r]; }
    __syncthreads();
    if (cs == 0) {
        float bb = b1[h];
        #pragma unroll
        for (int r = 0; r < 4; ++r) {
            P[(size_t)(base+r)*H_ + h] = sp[0][r][h] + sp[1][r][h] + bb;
            Q[(size_t)(base+r)*H_ + h] = sq[0][r][h] + sq[1][r][h];
        }
    }
}

// ---------------------------------------------------------------------------
// Merged prep: blocks [0,1024) E-convert; [1024,1184) weight prep (both
// layers); [1184,1440) pq for layer 1.  All independent.
// ---------------------------------------------------------------------------
__global__ void prep_all(const float* __restrict__ E,
                         const float* __restrict__ W1a, const float* __restrict__ W2a,
                         const float* __restrict__ W1b, const float* __restrict__ W2b,
                         const float* __restrict__ x0,  const float* __restrict__ b1a,
                         float* __restrict__ P, float* __restrict__ Q)
{
    const int blk = blockIdx.x, tid = threadIdx.x;
    if (blk < NBI) {
        unsigned short* eh = g_Ehi[blk];
        unsigned short* el = g_Elo[blk];
        for (int idx = tid; idx < 2048; idx += 256) {
            int j = idx >> 3, kq = idx & 7;
            float4 e4 = *(const float4*)(E + ((size_t)blk*V_ + j)*KE_ + kq*4);
            unsigned short h0=bf16b(e4.x), h1=bf16b(e4.y), h2=bf16b(e4.z), h3=bf16b(e4.w);
            uint2 hp, lp;
            hp.x = (uint32_t)h0 | ((uint32_t)h1 << 16);
            hp.y = (uint32_t)h2 | ((uint32_t)h3 << 16);
            lp.x = (uint32_t)bf16b(e4.x-bf16f(h0)) | ((uint32_t)bf16b(e4.y-bf16f(h1)) << 16);
            lp.y = (uint32_t)bf16b(e4.z-bf16f(h2)) | ((uint32_t)bf16b(e4.w-bf16f(h3)) << 16);
            int o = j*ST_E2 + kq*4;
            *(uint2*)(eh + o) = hp;
            *(uint2*)(el + o) = lp;
        }
    } else if (blk < NBI + 160) {
        int idx = (blk - NBI) * 256 + tid;      // [0, 40960)
        if (idx < 40960) {
            int layer = idx / 20480;
            int t = idx - layer * 20480;
            const float* W1 = layer ? W1b : W1a;
            const float* W2 = layer ? W2b : W2a;
            const int C = layer ? 128 : 64;
            if (t < KE_*H_) {
                int k = t >> 7, c = t & 127;
                float w = W1[(size_t)(2*C + k)*H_ + c];
                unsigned short h = bf16b(w);
                g_w1hi[layer][k*ST_W + c] = h;
                g_w1lo[layer][k*ST_W + c] = bf16b(w - bf16f(h));
            } else {
                int t2 = t - KE_*H_;
                int k = t2 >> 7, c = t2 & 127;
                float w = W2[(size_t)k*H_ + c];
                unsigned short h = bf16b(w);
                g_w2hi[layer][k*ST_W + c] = h;
                g_w2lo[layer][k*ST_W + c] = bf16b(w - bf16f(h));
            }
        }
    } else {
        pq_impl(blk - (NBI + 160), x0, W1a, b1a, 64, P, Q);
    }
}

__global__ void pq_kernel(const float* __restrict__ x, const float* __restrict__ W1,
                          const float* __restrict__ b1, int C_in,
                          float* __restrict__ P, float* __restrict__ Q)
{
    pq_impl(blockIdx.x, x, W1, b1, C_in, P, Q);
}

// ---------------------------------------------------------------------------
// Persistent-CTA fused EdgeConv on HMMA (unchanged mainloop from R7).
// ---------------------------------------------------------------------------
__global__ void __launch_bounds__(256, 1)
ec_hmma(const float* __restrict__ Pg, const float* __restrict__ Qg,
        const float* __restrict__ b2, const int* __restrict__ adj,
        float* __restrict__ Xout, int layer)
{
    extern __shared__ char smem[];
    const uint32_t sb = smem_to_u32(smem);
    const int tid = threadIdx.x, w = tid >> 5, lane = tid & 31;
    const int g = lane >> 2, tg = lane & 3;
    const int j0 = w * 16;
    const int rowsel = lane & 15, colsel = (lane >> 4) * 8;

    {   // stage weight tiles ONCE
        const uint4* s; uint4* d;
        s = (const uint4*)g_w1hi[layer]; d = (uint4*)(smem + OFF_W1HI);
        for (int i = tid; i < 544;  i += 256) d[i] = s[i];
        s = (const uint4*)g_w1lo[layer]; d = (uint4*)(smem + OFF_W1LO);
        for (int i = tid; i < 544;  i += 256) d[i] = s[i];
        s = (const uint4*)g_w2hi[layer]; d = (uint4*)(smem + OFF_W2HI);
        for (int i = tid; i < 2176; i += 256) d[i] = s[i];
        s = (const uint4*)g_w2lo[layer]; d = (uint4*)(smem + OFF_W2LO);
        for (int i = tid; i < 2176; i += 256) d[i] = s[i];
    }
    float* sPf  = (float*)(smem + OFF_P);
    float* sB2f = (float*)(smem + OFF_B2);
    int*   sAdj = (int*)(smem + OFF_ADJ);
    float* red  = (float*)(smem + OFF_RED);
    if (tid < H_) sB2f[tid] = b2[tid];

    int cur = 0;
    {
        const char* sh = (const char*)g_Ehi[blockIdx.x];
        const char* sl = (const char*)g_Elo[blockIdx.x];
        for (int i = tid; i < EBYTES/16; i += 256) {
            cp16(sb + OFF_E0 + i*16,          sh + i*16);
            cp16(sb + OFF_E0 + EBYTES + i*16, sl + i*16);
        }
        CP_COMMIT();
    }

    for (int bi = blockIdx.x; bi < NBI; bi += gridDim.x) {
        const int b = bi >> 8;
        const int nbi = bi + gridDim.x;
        // issue P/adj loads early so their latency hides under the cp wait
        float pv = (tid < H_) ? Pg[(size_t)bi*H_ + tid] : 0.f;
        int   av = adj[(size_t)bi*V_ + tid];
        if (nbi < NBI) {
            const int nb = 1 - cur;
            const char* sh = (const char*)g_Ehi[nbi];
            const char* sl = (const char*)g_Elo[nbi];
            for (int i = tid; i < EBYTES/16; i += 256) {
                cp16(sb + OFF_E0 + nb*EBUF_SZ + i*16,          sh + i*16);
                cp16(sb + OFF_E0 + nb*EBUF_SZ + EBYTES + i*16, sl + i*16);
            }
            CP_COMMIT();
            CP_WAIT1();
        } else {
            CP_WAIT0();
        }
        if (tid < H_) sPf[tid] = pv;
        sAdj[tid] = av;
        __syncthreads();

        const uint32_t eH = sb + OFF_E0 + cur*EBUF_SZ;
        const uint32_t eL = eH + EBYTES;

        float rmax[32];
        #pragma unroll
        for (int i = 0; i < 32; ++i) rmax[i] = -1e9f;

        #pragma unroll
        for (int chunk = 0; chunk < 2; ++chunk) {
            const int jbase = chunk * 128;

            float acc[16][4];
            #pragma unroll
            for (int n = 0; n < 16; ++n)
                #pragma unroll
                for (int p = 0; p < 4; ++p) acc[n][p] = 0.f;

            // ---- phase 1: E @ W1c (K=32) ----
            #pragma unroll
            for (int ks = 0; ks < 2; ++ks) {
                const int k0 = ks * 16;
                uint32_t aH[4], aL[4];
                uint32_t ao = (uint32_t)((jbase + j0 + rowsel)*ST_E2 + k0 + colsel) * 2u;
                ldsm4(aH, eH + ao);
                ldsm4(aL, eL + ao);
                const uint32_t brow = (uint32_t)((k0 + rowsel)*ST_W + colsel) * 2u;
                #pragma unroll
                for (int ntp = 0; ntp < 8; ++ntp) {
                    uint32_t bo = brow + (uint32_t)(ntp*16*2);
                    uint32_t bH[4], bL[4];
                    ldsm4t(bH, sb + OFF_W1HI + bo);
                    ldsm4t(bL, sb + OFF_W1LO + bo);
                    mma_bf16(acc[2*ntp],   aH, &bH[0]);
                    mma_bf16(acc[2*ntp+1], aH, &bH[2]);
                    mma_bf16(acc[2*ntp],   aH, &bL[0]);
                    mma_bf16(acc[2*ntp+1], aH, &bL[2]);
                    mma_bf16(acc[2*ntp],   aL, &bH[0]);
                    mma_bf16(acc[2*ntp+1], aL, &bH[2]);
                }
            }

            // ---- epilogue 1: T = relu(P + Q + D) -> A-fragments in registers ----
            uint32_t aH2[8][4], aL2[8][4];
            {
                const float* qA = Qg + ((size_t)(b*V_ + jbase + j0 + g))*H_;
                const float* qB = qA + 8*H_;
                #pragma unroll
                for (int ks = 0; ks < 8; ++ks) {
                    #pragma unroll
                    for (int h = 0; h < 2; ++h) {
                        const int nt = 2*ks + h;
                        const int c = nt*8 + tg*2;
                        float2 q0 = *(const float2*)(qA + c);
                        float2 q1 = *(const float2*)(qB + c);
                        float pc0 = sPf[c], pc1 = sPf[c+1];
                        float t0 = fmaxf(acc[nt][0] + pc0 + q0.x, 0.f);
                        float t1 = fmaxf(acc[nt][1] + pc1 + q0.y, 0.f);
                        float t2 = fmaxf(acc[nt][2] + pc0 + q1.x, 0.f);
                        float t3 = fmaxf(acc[nt][3] + pc1 + q1.y, 0.f);
                        unsigned short h0=bf16b(t0), h1=bf16b(t1), h2=bf16b(t2), h3=bf16b(t3);
                        aH2[ks][0 + 2*h] = (uint32_t)h0 | ((uint32_t)h1 << 16);
                        aH2[ks][1 + 2*h] = (uint32_t)h2 | ((uint32_t)h3 << 16);
                        aL2[ks][0 + 2*h] =
                            (uint32_t)bf16b(t0-bf16f(h0)) | ((uint32_t)bf16b(t1-bf16f(h1)) << 16);
                        aL2[ks][1 + 2*h] =
                            (uint32_t)bf16b(t2-bf16f(h2)) | ((uint32_t)bf16b(t3-bf16f(h3)) << 16);
                    }
                }
            }

            #pragma unroll
            for (int n = 0; n < 16; ++n)
                #pragma unroll
                for (int p = 0; p < 4; ++p) acc[n][p] = 0.f;

            // ---- phase 2: T @ W2 (K=128), A from registers ----
            #pragma unroll
            for (int ks = 0; ks < 8; ++ks) {
                const uint32_t brow = (uint32_t)((ks*16 + rowsel)*ST_W + colsel) * 2u;
                #pragma unroll
                for (int ntp = 0; ntp < 8; ++ntp) {
                    uint32_t bo = brow + (uint32_t)(ntp*16*2);
                    uint32_t bH[4], bL[4];
                    ldsm4t(bH, sb + OFF_W2HI + bo);
                    ldsm4t(bL, sb + OFF_W2LO + bo);
                    mma_bf16(acc[2*ntp],   aH2[ks], &bH[0]);
                    mma_bf16(acc[2*ntp+1], aH2[ks], &bH[2]);
                    mma_bf16(acc[2*ntp],   aH2[ks], &bL[0]);
                    mma_bf16(acc[2*ntp+1], aH2[ks], &bL[2]);
                    mma_bf16(acc[2*ntp],   aL2[ks], &bH[0]);
                    mma_bf16(acc[2*ntp+1], aL2[ks], &bH[2]);
                }
            }

            // ---- epilogue 2: relu(+b2), adjacency-masked col-max ----
            {
                const bool actA = sAdj[jbase + j0 + g] > 0;
                const bool actB = sAdj[jbase + j0 + 8 + g] > 0;
                #pragma unroll
                for (int nt = 0; nt < 16; ++nt) {
                    const int c = nt*8 + tg*2;
                    float b0 = sB2f[c], b1 = sB2f[c+1];
                    if (actA) {
                        rmax[2*nt]   = fmaxf(rmax[2*nt],   fmaxf(acc[nt][0]+b0, 0.f));
                        rmax[2*nt+1] = fmaxf(rmax[2*nt+1], fmaxf(acc[nt][1]+b1, 0.f));
                    }
                    if (actB) {
                        rmax[2*nt]   = fmaxf(rmax[2*nt],   fmaxf(acc[nt][2]+b0, 0.f));
                        rmax[2*nt+1] = fmaxf(rmax[2*nt+1], fmaxf(acc[nt][3]+b1, 0.f));
                    }
                }
            }
        }

        // reduce over g, then over warps via smem
        #pragma unroll
        for (int off = 4; off <= 16; off <<= 1)
            #pragma unroll
            for (int i = 0; i < 32; ++i)
                rmax[i] = fmaxf(rmax[i], __shfl_xor_sync(0xffffffffu, rmax[i], off));

        if (lane < 4) {
            #pragma unroll
            for (int nt = 0; nt < 16; ++nt) {
                red[w*H_ + nt*8 + lane*2]     = rmax[2*nt];
                red[w*H_ + nt*8 + lane*2 + 1] = rmax[2*nt+1];
            }
        }
        __syncthreads();
        if (tid < H_) {
            float v = red[tid];
            #pragma unroll
            for (int ww = 1; ww < 8; ++ww) v = fmaxf(v, red[ww*H_ + tid]);
            Xout[(size_t)bi*H_ + tid] = (v < -1e8f) ? 0.f : v;
        }
        __syncthreads();
        cur ^= 1;
    }
}

// ---------------------------------------------------------------------------
// rs: R = x@W3[0:128], S = x@W3[128:256]+b3. 512 thr = (cs:2, m:256), 4 nodes.
// ---------------------------------------------------------------------------
__global__ void __launch_bounds__(512)
rs_kernel(const float* __restrict__ x, const float* __restrict__ W3,
          const float* __restrict__ b3,
          float* __restrict__ R, float* __restrict__ S)
{
    __shared__ float sx[4][128];
    __shared__ float sr[2][4][256], ss[2][4][256];
    const int tid = threadIdx.x;
    const int cs = tid >> 8, m = tid & 255;
    const int base = blockIdx.x * 4;
    sx[tid >> 7][tid & 127] = x[(size_t)(base + (tid >> 7))*H_ + (tid & 127)];
    __syncthreads();

    const int c0 = cs * 64, c1 = c0 + 64;
    float r[4] = {0.f,0.f,0.f,0.f}, s[4] = {0.f,0.f,0.f,0.f};
    for (int c = c0; c < c1; ++c) {
        float wa = W3[c*H2_ + m], wb = W3[(128+c)*H2_ + m];
        #pragma unroll
        for (int rr = 0; rr < 4; ++rr) { r[rr] += sx[rr][c]*wa; s[rr] += sx[rr][c]*wb; }
    }
    #pragma unroll
    for (int rr = 0; rr < 4; ++rr) { sr[cs][rr][m] = r[rr]; ss[cs][rr][m] = s[rr]; }
    __syncthreads();
    if (cs == 0) {
        float bb = b3[m];
        #pragma unroll
        for (int rr = 0; rr < 4; ++rr) {
            R[(size_t)(base+rr)*H2_ + m] = sr[0][rr][m] + sr[1][rr][m];
            S[(size_t)(base+rr)*H2_ + m] = ss[0][rr][m] + ss[1][rr][m] + bb;
        }
    }
}

#define IL_ 8
#define MC_ 32
__global__ void __launch_bounds__(256)
pair_kernel(const float* __restrict__ R, const float* __restrict__ S,
            const float* __restrict__ outW, const float* __restrict__ outB,
            float* __restrict__ out)
{
    __shared__ float sR[V_][MC_+1];
    __shared__ float sS[IL_][MC_+1];
    __shared__ float sw[MC_];
    const int tid = threadIdx.x;
    const int b = blockIdx.y, i0 = blockIdx.x * IL_;
    float acc[IL_];
    #pragma unroll
    for (int il = 0; il < IL_; ++il) acc[il] = 0.f;

    for (int mc = 0; mc < H2_; mc += MC_) {
        __syncthreads();
        #pragma unroll 4
        for (int idx = tid; idx < V_*MC_; idx += 256) {
            int j = idx >> 5, mm = idx & (MC_-1);
            sR[j][mm] = R[((size_t)b*V_ + j)*H2_ + mc + mm];
        }
        if (tid < IL_*MC_) {
            int il = tid >> 5, mm = tid & (MC_-1);
            sS[il][mm] = S[((size_t)b*V_ + i0 + il)*H2_ + mc + mm];
        }
        if (tid < MC_) sw[tid] = outW[mc + tid];
        __syncthreads();
        #pragma unroll
        for (int il = 0; il < IL_; ++il) {
            float a = 0.f;
            #pragma unroll
            for (int mm = 0; mm < MC_; ++mm)
                a += fmaxf(sR[tid][mm] + sS[il][mm], 0.f) * sw[mm];
            acc[il] += a;
        }
    }
    const float ob = outB[0];
    #pragma unroll
    for (int il = 0; il < IL_; ++il) {
        float z = acc[il] + ob;
        out[((size_t)b*V_ + i0 + il)*V_ + tid] = 1.f / (1.f + expf(-z));
    }
}

// ---------------------------------------------------------------------------
extern "C" void kernel_launch(void* const* d_in, const int* in_sizes, int n_in,
                              void* d_out, int out_size)
{
    const int*   adj   = (const int*)  d_in[0];
    const float* x0    = (const float*)d_in[1];
    const float* e     = (const float*)d_in[2];
    const float* ec1W1 = (const float*)d_in[3];
    const float* ec1b1 = (const float*)d_in[4];
    const float* ec1W2 = (const float*)d_in[5];
    const float* ec1b2 = (const float*)d_in[6];
    const float* ec2W1 = (const float*)d_in[7];
    const float* ec2b1 = (const float*)d_in[8];
    const float* ec2W2 = (const float*)d_in[9];
    const float* ec2b2 = (const float*)d_in[10];
    const float* h3W   = (const float*)d_in[11];
    const float* h3b   = (const float*)d_in[12];
    const float* outW  = (const float*)d_in[13];
    const float* outB  = (const float*)d_in[14];
    float* out = (float*)d_out;

    float *P, *Q, *X1, *X2, *R, *S;
    cudaGetSymbolAddress((void**)&P,  g_P);
    cudaGetSymbolAddress((void**)&Q,  g_Q);
    cudaGetSymbolAddress((void**)&X1, g_X1);
    cudaGetSymbolAddress((void**)&X2, g_X2);
    cudaGetSymbolAddress((void**)&R,  g_R);
    cudaGetSymbolAddress((void**)&S,  g_S);

    cudaFuncSetAttribute(ec_hmma, cudaFuncAttributeMaxDynamicSharedMemorySize, SMEM_EC);

    int sms = 148;
    cudaDeviceGetAttribute(&sms, cudaDevAttrMultiProcessorCount, 0);
    int grid = sms < NBI ? sms : NBI;

    // 1 merged prep: E-convert + weight prep (both layers) + pq layer 1
    prep_all<<<NBI + 160 + 256, 256>>>(e, ec1W1, ec1W2, ec2W1, ec2W2, x0, ec1b1, P, Q);

    ec_hmma<<<grid, 256, SMEM_EC>>>(P, Q, ec1b2, adj, X1, 0);

    pq_kernel<<<NBI/4, 256>>>(X1, ec2W1, ec2b1, 128, P, Q);
    ec_hmma<<<grid, 256, SMEM_EC>>>(P, Q, ec2b2, adj, X2, 1);

    rs_kernel<<<NBI/4, 512>>>(X2, h3W, h3b, R, S);
    dim3 pg(V_/IL_, B_);
    pair_kernel<<<pg, 256>>>(R, S, outW, outB, out);
}